// round 3
// baseline (speedup 1.0000x reference)
#include <cuda_runtime.h>
#include <cuda_bf16.h>
#include <cstdint>

#define TOKS 4096
#define HID  2048
#define INTD 1024
#define NE   8

typedef __nv_bfloat16 bf16;

// ---------------- persistent device scratch ----------------------------------
__device__ int   g_counts[NE];
__device__ int   g_tok [NE * TOKS];
__device__ float g_wt  [NE * TOKS];
__device__ bf16  g_xsh [TOKS * HID];
__device__ bf16  g_xsl [TOKS * HID];
__device__ bf16  g_wgh [NE * INTD * HID];
__device__ bf16  g_wgl [NE * INTD * HID];
__device__ bf16  g_wuh [NE * INTD * HID];
__device__ bf16  g_wul [NE * INTD * HID];
__device__ bf16  g_wdh [NE * HID * INTD];
__device__ bf16  g_wdl [NE * HID * INTD];
__device__ bf16  g_acth[(size_t)NE * TOKS * INTD];
__device__ bf16  g_actl[(size_t)NE * TOKS * INTD];

// ---------------- asm helpers -------------------------------------------------
__device__ __forceinline__ uint32_t smem_u32(const void* p) {
    return (uint32_t)__cvta_generic_to_shared(p);
}

#define CPA(s, g)  asm volatile("cp.async.cg.shared.global [%0], [%1], 16;" :: "r"(s), "l"(g))
#define CPC()      asm volatile("cp.async.commit_group;" ::: "memory")
#define CPW2()     asm volatile("cp.async.wait_group 2;" ::: "memory")

#define LDM4(r, addr)                                                           \
    asm volatile("ldmatrix.sync.aligned.m8n8.x4.shared.b16 {%0,%1,%2,%3}, [%4];" \
        : "=r"((r)[0]), "=r"((r)[1]), "=r"((r)[2]), "=r"((r)[3]) : "r"(addr))

#define MMA(c, a, b0, b1)                                                       \
    asm volatile("mma.sync.aligned.m16n8k16.row.col.f32.bf16.bf16.f32 "          \
        "{%0,%1,%2,%3},{%4,%5,%6,%7},{%8,%9},{%0,%1,%2,%3};"                     \
        : "+f"((c)[0]), "+f"((c)[1]), "+f"((c)[2]), "+f"((c)[3])                 \
        : "r"((a)[0]), "r"((a)[1]), "r"((a)[2]), "r"((a)[3]), "r"(b0), "r"(b1))

// ================= kernel: zero out + counts ==================================
__global__ void __launch_bounds__(256) k_zero(float4* __restrict__ out, int n4) {
    int i = blockIdx.x * 256 + threadIdx.x;
    if (i < n4) out[i] = make_float4(0.f, 0.f, 0.f, 0.f);
    if (blockIdx.x == 0 && threadIdx.x < NE) g_counts[threadIdx.x] = 0;
}

// ================= kernel: fp32 -> bf16 hi/lo split ===========================
__global__ void __launch_bounds__(256)
k_split(const float4* __restrict__ src, bf16* __restrict__ hi,
        bf16* __restrict__ lo, int n4) {
    int i = blockIdx.x * 256 + threadIdx.x;
    if (i >= n4) return;
    float4 v = src[i];
    bf16 h0 = __float2bfloat16(v.x), h1 = __float2bfloat16(v.y);
    bf16 h2 = __float2bfloat16(v.z), h3 = __float2bfloat16(v.w);
    bf16 l0 = __float2bfloat16(v.x - __bfloat162float(h0));
    bf16 l1 = __float2bfloat16(v.y - __bfloat162float(h1));
    bf16 l2 = __float2bfloat16(v.z - __bfloat162float(h2));
    bf16 l3 = __float2bfloat16(v.w - __bfloat162float(h3));
    __nv_bfloat162 hp0; hp0.x = h0; hp0.y = h1;
    __nv_bfloat162 hp1; hp1.x = h2; hp1.y = h3;
    __nv_bfloat162 lp0; lp0.x = l0; lp0.y = l1;
    __nv_bfloat162 lp1; lp1.x = l2; lp1.y = l3;
    ((__nv_bfloat162*)(hi))[i * 2]     = hp0;
    ((__nv_bfloat162*)(hi))[i * 2 + 1] = hp1;
    ((__nv_bfloat162*)(lo))[i * 2]     = lp0;
    ((__nv_bfloat162*)(lo))[i * 2 + 1] = lp1;
}

// ================= kernel: router (warp per token) ============================
__global__ void __launch_bounds__(256) k_router(const float* __restrict__ x,
                                                const float* __restrict__ gw) {
    int t    = blockIdx.x * 8 + (threadIdx.x >> 5);
    int lane = threadIdx.x & 31;
    if (t >= TOKS) return;
    const float* h = x + (size_t)t * HID;

    float acc[NE];
#pragma unroll
    for (int e = 0; e < NE; e++) acc[e] = 0.0f;
    for (int i = lane; i < HID; i += 32) {
        float hv = h[i];
#pragma unroll
        for (int e = 0; e < NE; e++) acc[e] += hv * gw[e * HID + i];
    }
#pragma unroll
    for (int e = 0; e < NE; e++)
#pragma unroll
        for (int o = 16; o; o >>= 1) acc[e] += __shfl_xor_sync(0xFFFFFFFFu, acc[e], o);

    if (lane == 0) {
        float mx = acc[0];
#pragma unroll
        for (int e = 1; e < NE; e++) mx = fmaxf(mx, acc[e]);
        float p[NE], s = 0.0f;
#pragma unroll
        for (int e = 0; e < NE; e++) { p[e] = expf(acc[e] - mx); s += p[e]; }
#pragma unroll
        for (int e = 0; e < NE; e++) p[e] /= s;

        int i1 = 0;
#pragma unroll
        for (int e = 1; e < NE; e++) if (p[e] > p[i1]) i1 = e;
        int i2 = (i1 == 0) ? 1 : 0;
#pragma unroll
        for (int e = 0; e < NE; e++) if (e != i1 && p[e] > p[i2]) i2 = e;

        float denom = p[i1] + p[i2];
        int pos = atomicAdd(&g_counts[i1], 1);
        g_tok[i1 * TOKS + pos] = t;
        g_wt [i1 * TOKS + pos] = p[i1] / denom;
        pos = atomicAdd(&g_counts[i2], 1);
        g_tok[i2 * TOKS + pos] = t;
        g_wt [i2 * TOKS + pos] = p[i2] / denom;
    }
}

// ================= kernel: gate+up GEMM + SiLU ================================
// tiles: M=128 (tokens of expert e), N=64 inter cols (gate AND up), K=HID
// smem per stage (32KB): [Ahi 8K][Alo 8K][Bhi 8K: gate rows 0-63, up rows 64-127][Blo 8K]
#define STAGE_BYTES 32768
#define SMEM_MAIN   (3 * STAGE_BYTES)

__global__ void __launch_bounds__(256, 1)
k2_gateup() {
    extern __shared__ char smem[];
    const int e     = blockIdx.x >> 5;
    const int mtile = blockIdx.x & 31;
    const int ntile = blockIdx.y;
    const int cnt   = g_counts[e];
    if (mtile * 128 >= cnt) return;

    const int tid  = threadIdx.x;
    const int wid  = tid >> 5;
    const int lane = tid & 31;

    int* STOK = (int*)(smem + SMEM_MAIN);
    if (tid < 128) {
        int rp = mtile * 128 + tid;
        STOK[tid] = g_tok[e * TOKS + (rp < cnt ? rp : cnt - 1)];
    }
    __syncthreads();

    const uint32_t sb = smem_u32(smem);
    const bf16* wgh = g_wgh + ((size_t)e * INTD + (size_t)ntile * 64) * HID;
    const bf16* wgl = g_wgl + ((size_t)e * INTD + (size_t)ntile * 64) * HID;
    const bf16* wuh = g_wuh + ((size_t)e * INTD + (size_t)ntile * 64) * HID;
    const bf16* wul = g_wul + ((size_t)e * INTD + (size_t)ntile * 64) * HID;

    const uint32_t mloc = (lane & 7) | (((lane >> 3) & 1) << 3);
    const uint32_t csel = lane >> 4;
    const uint32_t wm = (wid & 1) * 64;
    const uint32_t wn = (wid >> 1) * 16;
    uint32_t aoff[4];
#pragma unroll
    for (int mt = 0; mt < 4; mt++) {
        uint32_t r = wm + mt * 16 + mloc;
        aoff[mt] = r * 64 + ((csel ^ ((r >> 1) & 3)) << 4);
    }
    const uint32_t brow = wn + mloc;
    const uint32_t boff = brow * 64 + ((csel ^ ((brow >> 1) & 3)) << 4);

    float cg[4][2][4] = {};
    float cu[4][2][4] = {};

    auto load_stage = [&](int stage, int kc) {
        const uint32_t st = sb + stage * STAGE_BYTES;
        const int k0 = kc * 32;
#pragma unroll
        for (int i = 0; i < 8; i++) {
            int q   = tid + i * 256;
            int buf = q >> 9;
            int rc  = q & 511;
            int row = rc >> 2;
            int ch  = rc & 3;
            uint32_t dst = st + buf * 8192 + row * 64 + ((ch ^ ((row >> 1) & 3)) << 4);
            const bf16* src;
            if (buf == 0)      src = g_xsh + (size_t)STOK[row] * HID + k0 + ch * 8;
            else if (buf == 1) src = g_xsl + (size_t)STOK[row] * HID + k0 + ch * 8;
            else if (buf == 2) src = (row < 64 ? wgh + (size_t)row * HID
                                               : wuh + (size_t)(row - 64) * HID) + k0 + ch * 8;
            else               src = (row < 64 ? wgl + (size_t)row * HID
                                               : wul + (size_t)(row - 64) * HID) + k0 + ch * 8;
            CPA(dst, src);
        }
    };

    load_stage(0, 0); CPC();
    load_stage(1, 1); CPC();

    for (int kc = 0; kc < HID / 32; kc++) {
        const int stage = kc % 3;
        if (kc + 2 < HID / 32) load_stage((kc + 2) % 3, kc + 2);
        CPC();
        CPW2();
        __syncthreads();

        const uint32_t sA = sb + stage * STAGE_BYTES;
        const uint32_t sB = sA + 16384;
#pragma unroll
        for (int ksx = 0; ksx < 64; ksx += 32) {
            uint32_t ah[4][4], al[4][4], gh[4], gl[4], uh[4], ul[4];
#pragma unroll
            for (int mt = 0; mt < 4; mt++) {
                LDM4(ah[mt], sA + (aoff[mt] ^ ksx));
                LDM4(al[mt], sA + 8192 + (aoff[mt] ^ ksx));
            }
            LDM4(gh, sB + (boff ^ ksx));
            LDM4(uh, sB + 4096 + (boff ^ ksx));
            LDM4(gl, sB + 8192 + (boff ^ ksx));
            LDM4(ul, sB + 12288 + (boff ^ ksx));
#pragma unroll
            for (int mt = 0; mt < 4; mt++)
#pragma unroll
                for (int nt = 0; nt < 2; nt++) {
                    MMA(cg[mt][nt], ah[mt], gh[nt], gh[nt + 2]);
                    MMA(cg[mt][nt], al[mt], gh[nt], gh[nt + 2]);
                    MMA(cg[mt][nt], ah[mt], gl[nt], gl[nt + 2]);
                    MMA(cu[mt][nt], ah[mt], uh[nt], uh[nt + 2]);
                    MMA(cu[mt][nt], al[mt], uh[nt], uh[nt + 2]);
                    MMA(cu[mt][nt], ah[mt], ul[nt], ul[nt + 2]);
                }
        }
        __syncthreads();
    }

    // epilogue: SiLU(g)*u -> bf16 hi/lo act scratch
#pragma unroll
    for (int mt = 0; mt < 4; mt++) {
        int p0 = mtile * 128 + wm + mt * 16 + (lane >> 2);
        int p1 = p0 + 8;
#pragma unroll
        for (int nt = 0; nt < 2; nt++) {
            int col = ntile * 64 + wn + nt * 8 + (lane & 3) * 2;
            float a0, a1, a2, a3, gv, uv;
            gv = cg[mt][nt][0]; uv = cu[mt][nt][0]; a0 = gv / (1.f + expf(-gv)) * uv;
            gv = cg[mt][nt][1]; uv = cu[mt][nt][1]; a1 = gv / (1.f + expf(-gv)) * uv;
            gv = cg[mt][nt][2]; uv = cu[mt][nt][2]; a2 = gv / (1.f + expf(-gv)) * uv;
            gv = cg[mt][nt][3]; uv = cu[mt][nt][3]; a3 = gv / (1.f + expf(-gv)) * uv;
            if (p0 < cnt) {
                size_t idx = ((size_t)e * TOKS + p0) * INTD + col;
                __nv_bfloat162 hp, lp;
                hp.x = __float2bfloat16(a0); hp.y = __float2bfloat16(a1);
                lp.x = __float2bfloat16(a0 - __bfloat162float(hp.x));
                lp.y = __float2bfloat16(a1 - __bfloat162float(hp.y));
                *(__nv_bfloat162*)(g_acth + idx) = hp;
                *(__nv_bfloat162*)(g_actl + idx) = lp;
            }
            if (p1 < cnt) {
                size_t idx = ((size_t)e * TOKS + p1) * INTD + col;
                __nv_bfloat162 hp, lp;
                hp.x = __float2bfloat16(a2); hp.y = __float2bfloat16(a3);
                lp.x = __float2bfloat16(a2 - __bfloat162float(hp.x));
                lp.y = __float2bfloat16(a3 - __bfloat162float(hp.y));
                *(__nv_bfloat162*)(g_acth + idx) = hp;
                *(__nv_bfloat162*)(g_actl + idx) = lp;
            }
        }
    }
}

// ================= kernel: down GEMM + weighted scatter-add ===================
// tiles: M=128 slot rows, N=128 hid cols, K=INTD
__global__ void __launch_bounds__(256, 1)
k3_down(float* __restrict__ out) {
    extern __shared__ char smem[];
    const int e     = blockIdx.x >> 5;
    const int mtile = blockIdx.x & 31;
    const int ntile = blockIdx.y;
    const int cnt   = g_counts[e];
    if (mtile * 128 >= cnt) return;

    const int tid  = threadIdx.x;
    const int wid  = tid >> 5;
    const int lane = tid & 31;

    const uint32_t sb = smem_u32(smem);
    const bf16* ath = g_acth + (size_t)e * TOKS * INTD;
    const bf16* atl = g_actl + (size_t)e * TOKS * INTD;
    const bf16* wdh = g_wdh + ((size_t)e * HID + (size_t)ntile * 128) * INTD;
    const bf16* wdl = g_wdl + ((size_t)e * HID + (size_t)ntile * 128) * INTD;

    const uint32_t mloc = (lane & 7) | (((lane >> 3) & 1) << 3);
    const uint32_t csel = lane >> 4;
    const uint32_t wm = (wid & 1) * 64;
    const uint32_t wn = (wid >> 1) * 32;
    uint32_t aoff[4];
#pragma unroll
    for (int mt = 0; mt < 4; mt++) {
        uint32_t r = wm + mt * 16 + mloc;
        aoff[mt] = r * 64 + ((csel ^ ((r >> 1) & 3)) << 4);
    }
    uint32_t boff[2];
#pragma unroll
    for (int i = 0; i < 2; i++) {
        uint32_t r = wn + i * 16 + mloc;
        boff[i] = r * 64 + ((csel ^ ((r >> 1) & 3)) << 4);
    }

    float cd[4][4][4] = {};

    auto load_stage = [&](int stage, int kc) {
        const uint32_t st = sb + stage * STAGE_BYTES;
        const int k0 = kc * 32;
#pragma unroll
        for (int i = 0; i < 8; i++) {
            int q   = tid + i * 256;
            int buf = q >> 9;
            int rc  = q & 511;
            int row = rc >> 2;
            int ch  = rc & 3;
            uint32_t dst = st + buf * 8192 + row * 64 + ((ch ^ ((row >> 1) & 3)) << 4);
            const bf16* src;
            if (buf < 2) {
                int rp = mtile * 128 + row;
                size_t arow = (size_t)(rp < cnt ? rp : cnt - 1) * INTD;
                src = (buf == 0 ? ath : atl) + arow + k0 + ch * 8;
            } else {
                src = (buf == 2 ? wdh : wdl) + (size_t)row * INTD + k0 + ch * 8;
            }
            CPA(dst, src);
        }
    };

    load_stage(0, 0); CPC();
    load_stage(1, 1); CPC();

    for (int kc = 0; kc < INTD / 32; kc++) {
        const int stage = kc % 3;
        if (kc + 2 < INTD / 32) load_stage((kc + 2) % 3, kc + 2);
        CPC();
        CPW2();
        __syncthreads();

        const uint32_t sA = sb + stage * STAGE_BYTES;
        const uint32_t sB = sA + 16384;
#pragma unroll
        for (int ksx = 0; ksx < 64; ksx += 32) {
            uint32_t ah[4][4], al[4][4], dh[8], dl[8];
#pragma unroll
            for (int mt = 0; mt < 4; mt++) {
                LDM4(ah[mt], sA + (aoff[mt] ^ ksx));
                LDM4(al[mt], sA + 8192 + (aoff[mt] ^ ksx));
            }
            LDM4(dh,     sB + (boff[0] ^ ksx));
            LDM4(dh + 4, sB + (boff[1] ^ ksx));
            LDM4(dl,     sB + 8192 + (boff[0] ^ ksx));
            LDM4(dl + 4, sB + 8192 + (boff[1] ^ ksx));
#pragma unroll
            for (int mt = 0; mt < 4; mt++)
#pragma unroll
                for (int nt = 0; nt < 4; nt++) {
                    int b0 = (nt >> 1) * 4 + (nt & 1);
                    MMA(cd[mt][nt], ah[mt], dh[b0], dh[b0 + 2]);
                    MMA(cd[mt][nt], al[mt], dh[b0], dh[b0 + 2]);
                    MMA(cd[mt][nt], ah[mt], dl[b0], dl[b0 + 2]);
                }
        }
        __syncthreads();
    }

    // epilogue: scale by routing weight, atomicAdd into out (2 commutative adds/elem)
#pragma unroll
    for (int mt = 0; mt < 4; mt++) {
        int p0 = mtile * 128 + wm + mt * 16 + (lane >> 2);
        int p1 = p0 + 8;
        bool v0 = p0 < cnt, v1 = p1 < cnt;
        float w0 = 0.f, w1 = 0.f;
        float *o0 = out, *o1 = out;
        if (v0) {
            w0 = g_wt[e * TOKS + p0];
            o0 = out + (size_t)g_tok[e * TOKS + p0] * HID + ntile * 128;
        }
        if (v1) {
            w1 = g_wt[e * TOKS + p1];
            o1 = out + (size_t)g_tok[e * TOKS + p1] * HID + ntile * 128;
        }
#pragma unroll
        for (int nt = 0; nt < 4; nt++) {
            int col = wn + nt * 8 + (lane & 3) * 2;
            if (v0) {
                atomicAdd(o0 + col,     w0 * cd[mt][nt][0]);
                atomicAdd(o0 + col + 1, w0 * cd[mt][nt][1]);
            }
            if (v1) {
                atomicAdd(o1 + col,     w1 * cd[mt][nt][2]);
                atomicAdd(o1 + col + 1, w1 * cd[mt][nt][3]);
            }
        }
    }
}

// ================= launch =====================================================
extern "C" void kernel_launch(void* const* d_in, const int* in_sizes, int n_in,
                              void* d_out, int out_size) {
    const float* x  = (const float*)d_in[0];
    const float* gw = (const float*)d_in[1];
    const float* wg = (const float*)d_in[2];
    const float* wu = (const float*)d_in[3];
    const float* wd = (const float*)d_in[4];
    float* out = (float*)d_out;

    bf16 *xsh, *xsl, *wgh, *wgl, *wuh, *wul, *wdh, *wdl;
    cudaGetSymbolAddress((void**)&xsh, g_xsh);
    cudaGetSymbolAddress((void**)&xsl, g_xsl);
    cudaGetSymbolAddress((void**)&wgh, g_wgh);
    cudaGetSymbolAddress((void**)&wgl, g_wgl);
    cudaGetSymbolAddress((void**)&wuh, g_wuh);
    cudaGetSymbolAddress((void**)&wul, g_wul);
    cudaGetSymbolAddress((void**)&wdh, g_wdh);
    cudaGetSymbolAddress((void**)&wdl, g_wdl);

    const int SMEM = SMEM_MAIN + 1024;
    static bool attr_set = false;
    cudaFuncSetAttribute(k2_gateup, cudaFuncAttributeMaxDynamicSharedMemorySize, SMEM);
    cudaFuncSetAttribute(k3_down,   cudaFuncAttributeMaxDynamicSharedMemorySize, SMEM);
    (void)attr_set;

    const int NW = NE * INTD * HID / 4;   // weight float4 count (gate/up)
    const int NX = TOKS * HID / 4;

    k_zero <<<(TOKS * HID / 4 + 255) / 256, 256>>>((float4*)out, TOKS * HID / 4);
    k_split<<<(NX + 255) / 256, 256>>>((const float4*)x,  xsh, xsl, NX);
    k_split<<<(NW + 255) / 256, 256>>>((const float4*)wg, wgh, wgl, NW);
    k_split<<<(NW + 255) / 256, 256>>>((const float4*)wu, wuh, wul, NW);
    k_split<<<(NW + 255) / 256, 256>>>((const float4*)wd, wdh, wdl, NW);
    k_router<<<TOKS / 8, 256>>>(x, gw);
    k2_gateup<<<dim3(NE * 32, INTD / 64), 256, SMEM>>>();
    k3_down  <<<dim3(NE * 32, HID / 128), 256, SMEM>>>(out);
}

// round 4
// speedup vs baseline: 1.6231x; 1.6231x over previous
#include <cuda_runtime.h>
#include <cuda_fp16.h>
#include <cstdint>

#define TOKS 4096
#define HID  2048
#define INTD 1024
#define NE   8

typedef __half fp16;

// ---------------- persistent device scratch ----------------------------------
__device__ int   g_counts[NE];
__device__ int   g_tok [NE * TOKS];
__device__ float g_wt  [NE * TOKS];
__device__ fp16  g_xsh [TOKS * HID];
__device__ fp16  g_xsl [TOKS * HID];
__device__ fp16  g_wgh [NE * INTD * HID];
__device__ fp16  g_wuh [NE * INTD * HID];
__device__ fp16  g_wdh [NE * HID * INTD];
__device__ fp16  g_acth[(size_t)NE * TOKS * INTD];
__device__ fp16  g_actl[(size_t)NE * TOKS * INTD];

// ---------------- asm helpers -------------------------------------------------
__device__ __forceinline__ uint32_t smem_u32(const void* p) {
    return (uint32_t)__cvta_generic_to_shared(p);
}

#define CPA(s, g)  asm volatile("cp.async.cg.shared.global [%0], [%1], 16;" :: "r"(s), "l"(g))
#define CPC()      asm volatile("cp.async.commit_group;" ::: "memory")
#define CPW2()     asm volatile("cp.async.wait_group 2;" ::: "memory")

#define LDM4(r, addr)                                                           \
    asm volatile("ldmatrix.sync.aligned.m8n8.x4.shared.b16 {%0,%1,%2,%3}, [%4];" \
        : "=r"((r)[0]), "=r"((r)[1]), "=r"((r)[2]), "=r"((r)[3]) : "r"(addr))

#define MMA(c, a, b0, b1)                                                       \
    asm volatile("mma.sync.aligned.m16n8k16.row.col.f32.f16.f16.f32 "            \
        "{%0,%1,%2,%3},{%4,%5,%6,%7},{%8,%9},{%0,%1,%2,%3};"                     \
        : "+f"((c)[0]), "+f"((c)[1]), "+f"((c)[2]), "+f"((c)[3])                 \
        : "r"((a)[0]), "r"((a)[1]), "r"((a)[2]), "r"((a)[3]), "r"(b0), "r"(b1))

// ================= kernel: zero out + counts ==================================
__global__ void __launch_bounds__(256) k_zero(float4* __restrict__ out, int n4) {
    int i = blockIdx.x * 256 + threadIdx.x;
    if (i < n4) out[i] = make_float4(0.f, 0.f, 0.f, 0.f);
    if (blockIdx.x == 0 && threadIdx.x < NE) g_counts[threadIdx.x] = 0;
}

// ================= kernel: fp32 -> fp16 hi/lo split (activations) =============
__global__ void __launch_bounds__(256)
k_split_hl(const float4* __restrict__ src, fp16* __restrict__ hi,
           fp16* __restrict__ lo, int n4) {
    int i = blockIdx.x * 256 + threadIdx.x;
    if (i >= n4) return;
    float4 v = src[i];
    fp16 h0 = __float2half_rn(v.x), h1 = __float2half_rn(v.y);
    fp16 h2 = __float2half_rn(v.z), h3 = __float2half_rn(v.w);
    __half2 hp0, hp1, lp0, lp1;
    hp0.x = h0; hp0.y = h1; hp1.x = h2; hp1.y = h3;
    lp0.x = __float2half_rn(v.x - __half2float(h0));
    lp0.y = __float2half_rn(v.y - __half2float(h1));
    lp1.x = __float2half_rn(v.z - __half2float(h2));
    lp1.y = __float2half_rn(v.w - __half2float(h3));
    ((__half2*)hi)[i * 2]     = hp0;
    ((__half2*)hi)[i * 2 + 1] = hp1;
    ((__half2*)lo)[i * 2]     = lp0;
    ((__half2*)lo)[i * 2 + 1] = lp1;
}

// ================= kernel: fp32 -> fp16 round (weights, hi only) ==============
__global__ void __launch_bounds__(256)
k_split_h(const float4* __restrict__ src, fp16* __restrict__ hi, int n4) {
    int i = blockIdx.x * 256 + threadIdx.x;
    if (i >= n4) return;
    float4 v = src[i];
    __half2 hp0, hp1;
    hp0.x = __float2half_rn(v.x); hp0.y = __float2half_rn(v.y);
    hp1.x = __float2half_rn(v.z); hp1.y = __float2half_rn(v.w);
    ((__half2*)hi)[i * 2]     = hp0;
    ((__half2*)hi)[i * 2 + 1] = hp1;
}

// ================= kernel: router (warp per token) ============================
__global__ void __launch_bounds__(256) k_router(const float* __restrict__ x,
                                                const float* __restrict__ gw) {
    int t    = blockIdx.x * 8 + (threadIdx.x >> 5);
    int lane = threadIdx.x & 31;
    if (t >= TOKS) return;
    const float* h = x + (size_t)t * HID;

    float acc[NE];
#pragma unroll
    for (int e = 0; e < NE; e++) acc[e] = 0.0f;
    for (int i = lane; i < HID; i += 32) {
        float hv = h[i];
#pragma unroll
        for (int e = 0; e < NE; e++) acc[e] += hv * gw[e * HID + i];
    }
#pragma unroll
    for (int e = 0; e < NE; e++)
#pragma unroll
        for (int o = 16; o; o >>= 1) acc[e] += __shfl_xor_sync(0xFFFFFFFFu, acc[e], o);

    if (lane == 0) {
        float mx = acc[0];
#pragma unroll
        for (int e = 1; e < NE; e++) mx = fmaxf(mx, acc[e]);
        float p[NE], s = 0.0f;
#pragma unroll
        for (int e = 0; e < NE; e++) { p[e] = expf(acc[e] - mx); s += p[e]; }
#pragma unroll
        for (int e = 0; e < NE; e++) p[e] /= s;

        int i1 = 0;
#pragma unroll
        for (int e = 1; e < NE; e++) if (p[e] > p[i1]) i1 = e;
        int i2 = (i1 == 0) ? 1 : 0;
#pragma unroll
        for (int e = 0; e < NE; e++) if (e != i1 && p[e] > p[i2]) i2 = e;

        float denom = p[i1] + p[i2];
        int pos = atomicAdd(&g_counts[i1], 1);
        g_tok[i1 * TOKS + pos] = t;
        g_wt [i1 * TOKS + pos] = p[i1] / denom;
        pos = atomicAdd(&g_counts[i2], 1);
        g_tok[i2 * TOKS + pos] = t;
        g_wt [i2 * TOKS + pos] = p[i2] / denom;
    }
}

// ================= kernel: gate+up GEMM + SiLU ================================
// tiles: M=128 tokens, N=64 inter cols (gate AND up), K=HID, BK=32
// stage (24KB): [Ahi 8K][Alo 8K][B 8K: gate rows 0-63, up rows 64-127]
#define STAGE_BYTES 24576
#define SMEM_MAIN   (3 * STAGE_BYTES)

__global__ void __launch_bounds__(256, 1)
k2_gateup() {
    extern __shared__ char smem[];
    const int e     = blockIdx.x >> 5;
    const int mtile = blockIdx.x & 31;
    const int ntile = blockIdx.y;
    const int cnt   = g_counts[e];
    if (mtile * 128 >= cnt) return;

    const int tid  = threadIdx.x;
    const int wid  = tid >> 5;
    const int lane = tid & 31;

    int* STOK = (int*)(smem + SMEM_MAIN);
    if (tid < 128) {
        int rp = mtile * 128 + tid;
        STOK[tid] = g_tok[e * TOKS + (rp < cnt ? rp : cnt - 1)];
    }
    __syncthreads();

    const uint32_t sb = smem_u32(smem);
    const fp16* wgh = g_wgh + ((size_t)e * INTD + (size_t)ntile * 64) * HID;
    const fp16* wuh = g_wuh + ((size_t)e * INTD + (size_t)ntile * 64) * HID;

    const uint32_t mloc = (lane & 7) | (((lane >> 3) & 1) << 3);
    const uint32_t csel = lane >> 4;
    const uint32_t wm = (wid & 1) * 64;
    const uint32_t wn = (wid >> 1) * 16;
    uint32_t aoff[4];
#pragma unroll
    for (int mt = 0; mt < 4; mt++) {
        uint32_t r = wm + mt * 16 + mloc;
        aoff[mt] = r * 64 + ((csel ^ ((r >> 1) & 3)) << 4);
    }
    const uint32_t brow = wn + mloc;
    const uint32_t boff = brow * 64 + ((csel ^ ((brow >> 1) & 3)) << 4);

    float cg[4][2][4] = {};
    float cu[4][2][4] = {};

    auto load_stage = [&](int stage, int kc) {
        const uint32_t st = sb + stage * STAGE_BYTES;
        const int k0 = kc * 32;
#pragma unroll
        for (int i = 0; i < 6; i++) {
            int q   = tid + i * 256;
            int buf = q >> 9;
            int rc  = q & 511;
            int row = rc >> 2;
            int ch  = rc & 3;
            uint32_t dst = st + buf * 8192 + row * 64 + ((ch ^ ((row >> 1) & 3)) << 4);
            const fp16* src;
            if (buf == 0)      src = g_xsh + (size_t)STOK[row] * HID + k0 + ch * 8;
            else if (buf == 1) src = g_xsl + (size_t)STOK[row] * HID + k0 + ch * 8;
            else               src = (row < 64 ? wgh + (size_t)row * HID
                                               : wuh + (size_t)(row - 64) * HID) + k0 + ch * 8;
            CPA(dst, src);
        }
    };

    load_stage(0, 0); CPC();
    load_stage(1, 1); CPC();

    for (int kc = 0; kc < HID / 32; kc++) {
        const int stage = kc % 3;
        if (kc + 2 < HID / 32) load_stage((kc + 2) % 3, kc + 2);
        CPC();
        CPW2();
        __syncthreads();

        const uint32_t sA = sb + stage * STAGE_BYTES;
        const uint32_t sB = sA + 16384;
#pragma unroll
        for (int ksx = 0; ksx < 64; ksx += 32) {
            uint32_t ah[4][4], al[4][4], gh[4], uh[4];
#pragma unroll
            for (int mt = 0; mt < 4; mt++) {
                LDM4(ah[mt], sA + (aoff[mt] ^ ksx));
                LDM4(al[mt], sA + 8192 + (aoff[mt] ^ ksx));
            }
            LDM4(gh, sB + (boff ^ ksx));
            LDM4(uh, sB + 4096 + (boff ^ ksx));
#pragma unroll
            for (int mt = 0; mt < 4; mt++)
#pragma unroll
                for (int nt = 0; nt < 2; nt++) {
                    MMA(cg[mt][nt], ah[mt], gh[nt], gh[nt + 2]);
                    MMA(cg[mt][nt], al[mt], gh[nt], gh[nt + 2]);
                    MMA(cu[mt][nt], ah[mt], uh[nt], uh[nt + 2]);
                    MMA(cu[mt][nt], al[mt], uh[nt], uh[nt + 2]);
                }
        }
        __syncthreads();
    }

    // epilogue: SiLU(g)*u -> fp16 hi/lo act scratch
#pragma unroll
    for (int mt = 0; mt < 4; mt++) {
        int p0 = mtile * 128 + wm + mt * 16 + (lane >> 2);
        int p1 = p0 + 8;
#pragma unroll
        for (int nt = 0; nt < 2; nt++) {
            int col = ntile * 64 + wn + nt * 8 + (lane & 3) * 2;
            float a0, a1, a2, a3, gv, uv;
            gv = cg[mt][nt][0]; uv = cu[mt][nt][0]; a0 = gv / (1.f + expf(-gv)) * uv;
            gv = cg[mt][nt][1]; uv = cu[mt][nt][1]; a1 = gv / (1.f + expf(-gv)) * uv;
            gv = cg[mt][nt][2]; uv = cu[mt][nt][2]; a2 = gv / (1.f + expf(-gv)) * uv;
            gv = cg[mt][nt][3]; uv = cu[mt][nt][3]; a3 = gv / (1.f + expf(-gv)) * uv;
            if (p0 < cnt) {
                size_t idx = ((size_t)e * TOKS + p0) * INTD + col;
                __half2 hp, lp;
                hp.x = __float2half_rn(a0); hp.y = __float2half_rn(a1);
                lp.x = __float2half_rn(a0 - __half2float(hp.x));
                lp.y = __float2half_rn(a1 - __half2float(hp.y));
                *(__half2*)(g_acth + idx) = hp;
                *(__half2*)(g_actl + idx) = lp;
            }
            if (p1 < cnt) {
                size_t idx = ((size_t)e * TOKS + p1) * INTD + col;
                __half2 hp, lp;
                hp.x = __float2half_rn(a2); hp.y = __float2half_rn(a3);
                lp.x = __float2half_rn(a2 - __half2float(hp.x));
                lp.y = __float2half_rn(a3 - __half2float(hp.y));
                *(__half2*)(g_acth + idx) = hp;
                *(__half2*)(g_actl + idx) = lp;
            }
        }
    }
}

// ================= kernel: down GEMM + weighted scatter-add ===================
// tiles: M=128 slot rows, N=128 hid cols, K=INTD, BK=32
// stage (24KB): [Ahi 8K][Alo 8K][W 8K]
__global__ void __launch_bounds__(256, 1)
k3_down(float* __restrict__ out) {
    extern __shared__ char smem[];
    const int e     = blockIdx.x >> 5;
    const int mtile = blockIdx.x & 31;
    const int ntile = blockIdx.y;
    const int cnt   = g_counts[e];
    if (mtile * 128 >= cnt) return;

    const int tid  = threadIdx.x;
    const int wid  = tid >> 5;
    const int lane = tid & 31;

    const uint32_t sb = smem_u32(smem);
    const fp16* ath = g_acth + (size_t)e * TOKS * INTD;
    const fp16* atl = g_actl + (size_t)e * TOKS * INTD;
    const fp16* wdh = g_wdh + ((size_t)e * HID + (size_t)ntile * 128) * INTD;

    const uint32_t mloc = (lane & 7) | (((lane >> 3) & 1) << 3);
    const uint32_t csel = lane >> 4;
    const uint32_t wm = (wid & 1) * 64;
    const uint32_t wn = (wid >> 1) * 32;
    uint32_t aoff[4];
#pragma unroll
    for (int mt = 0; mt < 4; mt++) {
        uint32_t r = wm + mt * 16 + mloc;
        aoff[mt] = r * 64 + ((csel ^ ((r >> 1) & 3)) << 4);
    }
    uint32_t boff[2];
#pragma unroll
    for (int i = 0; i < 2; i++) {
        uint32_t r = wn + i * 16 + mloc;
        boff[i] = r * 64 + ((csel ^ ((r >> 1) & 3)) << 4);
    }

    float cd[4][4][4] = {};

    auto load_stage = [&](int stage, int kc) {
        const uint32_t st = sb + stage * STAGE_BYTES;
        const int k0 = kc * 32;
#pragma unroll
        for (int i = 0; i < 6; i++) {
            int q   = tid + i * 256;
            int buf = q >> 9;
            int rc  = q & 511;
            int row = rc >> 2;
            int ch  = rc & 3;
            uint32_t dst = st + buf * 8192 + row * 64 + ((ch ^ ((row >> 1) & 3)) << 4);
            const fp16* src;
            if (buf < 2) {
                int rp = mtile * 128 + row;
                size_t arow = (size_t)(rp < cnt ? rp : cnt - 1) * INTD;
                src = (buf == 0 ? ath : atl) + arow + k0 + ch * 8;
            } else {
                src = wdh + (size_t)row * INTD + k0 + ch * 8;
            }
            CPA(dst, src);
        }
    };

    load_stage(0, 0); CPC();
    load_stage(1, 1); CPC();

    for (int kc = 0; kc < INTD / 32; kc++) {
        const int stage = kc % 3;
        if (kc + 2 < INTD / 32) load_stage((kc + 2) % 3, kc + 2);
        CPC();
        CPW2();
        __syncthreads();

        const uint32_t sA = sb + stage * STAGE_BYTES;
        const uint32_t sB = sA + 16384;
#pragma unroll
        for (int ksx = 0; ksx < 64; ksx += 32) {
            uint32_t ah[4][4], al[4][4], dh[8];
#pragma unroll
            for (int mt = 0; mt < 4; mt++) {
                LDM4(ah[mt], sA + (aoff[mt] ^ ksx));
                LDM4(al[mt], sA + 8192 + (aoff[mt] ^ ksx));
            }
            LDM4(dh,     sB + (boff[0] ^ ksx));
            LDM4(dh + 4, sB + (boff[1] ^ ksx));
#pragma unroll
            for (int mt = 0; mt < 4; mt++)
#pragma unroll
                for (int nt = 0; nt < 4; nt++) {
                    int b0 = (nt >> 1) * 4 + (nt & 1);
                    MMA(cd[mt][nt], ah[mt], dh[b0], dh[b0 + 2]);
                    MMA(cd[mt][nt], al[mt], dh[b0], dh[b0 + 2]);
                }
        }
        __syncthreads();
    }

    // epilogue: scale by routing weight, atomicAdd into out (2 commutative adds/elem)
#pragma unroll
    for (int mt = 0; mt < 4; mt++) {
        int p0 = mtile * 128 + wm + mt * 16 + (lane >> 2);
        int p1 = p0 + 8;
        bool v0 = p0 < cnt, v1 = p1 < cnt;
        float w0 = 0.f, w1 = 0.f;
        float *o0 = out, *o1 = out;
        if (v0) {
            w0 = g_wt[e * TOKS + p0];
            o0 = out + (size_t)g_tok[e * TOKS + p0] * HID + ntile * 128;
        }
        if (v1) {
            w1 = g_wt[e * TOKS + p1];
            o1 = out + (size_t)g_tok[e * TOKS + p1] * HID + ntile * 128;
        }
#pragma unroll
        for (int nt = 0; nt < 4; nt++) {
            int col = wn + nt * 8 + (lane & 3) * 2;
            if (v0) {
                atomicAdd(o0 + col,     w0 * cd[mt][nt][0]);
                atomicAdd(o0 + col + 1, w0 * cd[mt][nt][1]);
            }
            if (v1) {
                atomicAdd(o1 + col,     w1 * cd[mt][nt][2]);
                atomicAdd(o1 + col + 1, w1 * cd[mt][nt][3]);
            }
        }
    }
}

// ================= launch =====================================================
extern "C" void kernel_launch(void* const* d_in, const int* in_sizes, int n_in,
                              void* d_out, int out_size) {
    const float* x  = (const float*)d_in[0];
    const float* gw = (const float*)d_in[1];
    const float* wg = (const float*)d_in[2];
    const float* wu = (const float*)d_in[3];
    const float* wd = (const float*)d_in[4];
    float* out = (float*)d_out;

    fp16 *xsh, *xsl, *wgh, *wuh, *wdh;
    cudaGetSymbolAddress((void**)&xsh, g_xsh);
    cudaGetSymbolAddress((void**)&xsl, g_xsl);
    cudaGetSymbolAddress((void**)&wgh, g_wgh);
    cudaGetSymbolAddress((void**)&wuh, g_wuh);
    cudaGetSymbolAddress((void**)&wdh, g_wdh);

    const int SMEM = SMEM_MAIN + 1024;
    cudaFuncSetAttribute(k2_gateup, cudaFuncAttributeMaxDynamicSharedMemorySize, SMEM);
    cudaFuncSetAttribute(k3_down,   cudaFuncAttributeMaxDynamicSharedMemorySize, SMEM);

    const int NW = NE * INTD * HID / 4;   // weight float4 count
    const int NX = TOKS * HID / 4;

    k_zero <<<(TOKS * HID / 4 + 255) / 256, 256>>>((float4*)out, TOKS * HID / 4);
    k_split_hl<<<(NX + 255) / 256, 256>>>((const float4*)x,  xsh, xsl, NX);
    k_split_h <<<(NW + 255) / 256, 256>>>((const float4*)wg, wgh, NW);
    k_split_h <<<(NW + 255) / 256, 256>>>((const float4*)wu, wuh, NW);
    k_split_h <<<(NW + 255) / 256, 256>>>((const float4*)wd, wdh, NW);
    k_router<<<TOKS / 8, 256>>>(x, gw);
    k2_gateup<<<dim3(NE * 32, INTD / 64), 256, SMEM>>>();
    k3_down  <<<dim3(NE * 32, HID / 128), 256, SMEM>>>(out);
}

// round 5
// speedup vs baseline: 2.5916x; 1.5967x over previous
#include <cuda_runtime.h>
#include <cuda_fp16.h>
#include <cstdint>

#define TOKS 4096
#define HID  2048
#define INTD 1024
#define NE   8

typedef __half fp16;

// ---------------- persistent device scratch ----------------------------------
__device__ int   g_counts[NE];
__device__ int   g_tok [NE * TOKS];
__device__ float g_wt  [NE * TOKS];
__device__ fp16  g_xsh [TOKS * HID];
__device__ fp16  g_wgh [NE * INTD * HID];
__device__ fp16  g_wuh [NE * INTD * HID];
__device__ fp16  g_wdh [NE * HID * INTD];
__device__ fp16  g_acth[(size_t)NE * TOKS * INTD];

// ---------------- asm helpers -------------------------------------------------
__device__ __forceinline__ uint32_t smem_u32(const void* p) {
    return (uint32_t)__cvta_generic_to_shared(p);
}

#define CPA(s, g)  asm volatile("cp.async.cg.shared.global [%0], [%1], 16;" :: "r"(s), "l"(g))
#define CPC()      asm volatile("cp.async.commit_group;" ::: "memory")
#define CPW2()     asm volatile("cp.async.wait_group 2;" ::: "memory")

#define LDM4(r, addr)                                                           \
    asm volatile("ldmatrix.sync.aligned.m8n8.x4.shared.b16 {%0,%1,%2,%3}, [%4];" \
        : "=r"((r)[0]), "=r"((r)[1]), "=r"((r)[2]), "=r"((r)[3]) : "r"(addr))

#define MMA(c, a, b0, b1)                                                       \
    asm volatile("mma.sync.aligned.m16n8k16.row.col.f32.f16.f16.f32 "            \
        "{%0,%1,%2,%3},{%4,%5,%6,%7},{%8,%9},{%0,%1,%2,%3};"                     \
        : "+f"((c)[0]), "+f"((c)[1]), "+f"((c)[2]), "+f"((c)[3])                 \
        : "r"((a)[0]), "r"((a)[1]), "r"((a)[2]), "r"((a)[3]), "r"(b0), "r"(b1))

// ================= kernel: zero out + counts ==================================
__global__ void __launch_bounds__(256) k_zero(float4* __restrict__ out, int n4) {
    int i = blockIdx.x * 256 + threadIdx.x;
    if (i < n4) out[i] = make_float4(0.f, 0.f, 0.f, 0.f);
    if (blockIdx.x == 0 && threadIdx.x < NE) g_counts[threadIdx.x] = 0;
}

// ================= kernel: fp32 -> fp16 round =================================
__global__ void __launch_bounds__(256)
k_split_h(const float4* __restrict__ src, fp16* __restrict__ hi, int n4) {
    int i = blockIdx.x * 256 + threadIdx.x;
    if (i >= n4) return;
    float4 v = src[i];
    __half2 hp0, hp1;
    hp0.x = __float2half_rn(v.x); hp0.y = __float2half_rn(v.y);
    hp1.x = __float2half_rn(v.z); hp1.y = __float2half_rn(v.w);
    ((__half2*)hi)[i * 2]     = hp0;
    ((__half2*)hi)[i * 2 + 1] = hp1;
}

// ================= kernel: router (warp per token) ============================
__global__ void __launch_bounds__(256) k_router(const float* __restrict__ x,
                                                const float* __restrict__ gw) {
    int t    = blockIdx.x * 8 + (threadIdx.x >> 5);
    int lane = threadIdx.x & 31;
    if (t >= TOKS) return;
    const float* h = x + (size_t)t * HID;

    float acc[NE];
#pragma unroll
    for (int e = 0; e < NE; e++) acc[e] = 0.0f;
    for (int i = lane; i < HID; i += 32) {
        float hv = h[i];
#pragma unroll
        for (int e = 0; e < NE; e++) acc[e] += hv * gw[e * HID + i];
    }
#pragma unroll
    for (int e = 0; e < NE; e++)
#pragma unroll
        for (int o = 16; o; o >>= 1) acc[e] += __shfl_xor_sync(0xFFFFFFFFu, acc[e], o);

    if (lane == 0) {
        float mx = acc[0];
#pragma unroll
        for (int e = 1; e < NE; e++) mx = fmaxf(mx, acc[e]);
        float p[NE], s = 0.0f;
#pragma unroll
        for (int e = 0; e < NE; e++) { p[e] = expf(acc[e] - mx); s += p[e]; }
#pragma unroll
        for (int e = 0; e < NE; e++) p[e] /= s;

        int i1 = 0;
#pragma unroll
        for (int e = 1; e < NE; e++) if (p[e] > p[i1]) i1 = e;
        int i2 = (i1 == 0) ? 1 : 0;
#pragma unroll
        for (int e = 0; e < NE; e++) if (e != i1 && p[e] > p[i2]) i2 = e;

        float denom = p[i1] + p[i2];
        int pos = atomicAdd(&g_counts[i1], 1);
        g_tok[i1 * TOKS + pos] = t;
        g_wt [i1 * TOKS + pos] = p[i1] / denom;
        pos = atomicAdd(&g_counts[i2], 1);
        g_tok[i2 * TOKS + pos] = t;
        g_wt [i2 * TOKS + pos] = p[i2] / denom;
    }
}

// ================= kernel: gate+up GEMM + SiLU ================================
// tiles: M=128 tokens, N=64 inter cols (gate AND up), K=HID, BK=32
// stage (16KB): [A 8K][B 8K: gate rows 0-63, up rows 64-127]
#define STAGE_BYTES 16384
#define SMEM_MAIN   (3 * STAGE_BYTES)

__global__ void __launch_bounds__(256, 1)
k2_gateup() {
    extern __shared__ char smem[];
    const int e     = blockIdx.x >> 5;
    const int mtile = blockIdx.x & 31;
    const int ntile = blockIdx.y;
    const int cnt   = g_counts[e];
    if (mtile * 128 >= cnt) return;

    const int tid  = threadIdx.x;
    const int wid  = tid >> 5;
    const int lane = tid & 31;

    int* STOK = (int*)(smem + SMEM_MAIN);
    if (tid < 128) {
        int rp = mtile * 128 + tid;
        STOK[tid] = g_tok[e * TOKS + (rp < cnt ? rp : cnt - 1)];
    }
    __syncthreads();

    const uint32_t sb = smem_u32(smem);
    const fp16* wgh = g_wgh + ((size_t)e * INTD + (size_t)ntile * 64) * HID;
    const fp16* wuh = g_wuh + ((size_t)e * INTD + (size_t)ntile * 64) * HID;

    const uint32_t mloc = (lane & 7) | (((lane >> 3) & 1) << 3);
    const uint32_t csel = lane >> 4;
    const uint32_t wm = (wid & 1) * 64;
    const uint32_t wn = (wid >> 1) * 16;
    uint32_t aoff[4];
#pragma unroll
    for (int mt = 0; mt < 4; mt++) {
        uint32_t r = wm + mt * 16 + mloc;
        aoff[mt] = r * 64 + ((csel ^ ((r >> 1) & 3)) << 4);
    }
    const uint32_t brow = wn + mloc;
    const uint32_t boff = brow * 64 + ((csel ^ ((brow >> 1) & 3)) << 4);

    float cg[4][2][4] = {};
    float cu[4][2][4] = {};

    auto load_stage = [&](int stage, int kc) {
        const uint32_t st = sb + stage * STAGE_BYTES;
        const int k0 = kc * 32;
#pragma unroll
        for (int i = 0; i < 4; i++) {
            int q   = tid + i * 256;
            int buf = q >> 9;
            int rc  = q & 511;
            int row = rc >> 2;
            int ch  = rc & 3;
            uint32_t dst = st + buf * 8192 + row * 64 + ((ch ^ ((row >> 1) & 3)) << 4);
            const fp16* src;
            if (buf == 0) src = g_xsh + (size_t)STOK[row] * HID + k0 + ch * 8;
            else          src = (row < 64 ? wgh + (size_t)row * HID
                                          : wuh + (size_t)(row - 64) * HID) + k0 + ch * 8;
            CPA(dst, src);
        }
    };

    load_stage(0, 0); CPC();
    load_stage(1, 1); CPC();

    for (int kc = 0; kc < HID / 32; kc++) {
        const int stage = kc % 3;
        if (kc + 2 < HID / 32) load_stage((kc + 2) % 3, kc + 2);
        CPC();
        CPW2();
        __syncthreads();

        const uint32_t sA = sb + stage * STAGE_BYTES;
        const uint32_t sB = sA + 8192;
#pragma unroll
        for (int ksx = 0; ksx < 64; ksx += 32) {
            uint32_t ah[4][4], gh[4], uh[4];
#pragma unroll
            for (int mt = 0; mt < 4; mt++) LDM4(ah[mt], sA + (aoff[mt] ^ ksx));
            LDM4(gh, sB + (boff ^ ksx));
            LDM4(uh, sB + 4096 + (boff ^ ksx));
#pragma unroll
            for (int mt = 0; mt < 4; mt++)
#pragma unroll
                for (int nt = 0; nt < 2; nt++) {
                    MMA(cg[mt][nt], ah[mt], gh[nt], gh[nt + 2]);
                    MMA(cu[mt][nt], ah[mt], uh[nt], uh[nt + 2]);
                }
        }
        __syncthreads();
    }

    // epilogue: SiLU(g)*u -> fp16 act scratch
#pragma unroll
    for (int mt = 0; mt < 4; mt++) {
        int p0 = mtile * 128 + wm + mt * 16 + (lane >> 2);
        int p1 = p0 + 8;
#pragma unroll
        for (int nt = 0; nt < 2; nt++) {
            int col = ntile * 64 + wn + nt * 8 + (lane & 3) * 2;
            float a0, a1, a2, a3, gv, uv;
            gv = cg[mt][nt][0]; uv = cu[mt][nt][0]; a0 = gv / (1.f + expf(-gv)) * uv;
            gv = cg[mt][nt][1]; uv = cu[mt][nt][1]; a1 = gv / (1.f + expf(-gv)) * uv;
            gv = cg[mt][nt][2]; uv = cu[mt][nt][2]; a2 = gv / (1.f + expf(-gv)) * uv;
            gv = cg[mt][nt][3]; uv = cu[mt][nt][3]; a3 = gv / (1.f + expf(-gv)) * uv;
            if (p0 < cnt) {
                size_t idx = ((size_t)e * TOKS + p0) * INTD + col;
                __half2 hp;
                hp.x = __float2half_rn(a0); hp.y = __float2half_rn(a1);
                *(__half2*)(g_acth + idx) = hp;
            }
            if (p1 < cnt) {
                size_t idx = ((size_t)e * TOKS + p1) * INTD + col;
                __half2 hp;
                hp.x = __float2half_rn(a2); hp.y = __float2half_rn(a3);
                *(__half2*)(g_acth + idx) = hp;
            }
        }
    }
}

// ================= kernel: down GEMM + weighted scatter-add ===================
// tiles: M=128 slot rows, N=128 hid cols, K=INTD, BK=32
// stage (16KB): [A 8K][W 8K]
__global__ void __launch_bounds__(256, 1)
k3_down(float* __restrict__ out) {
    extern __shared__ char smem[];
    const int e     = blockIdx.x >> 5;
    const int mtile = blockIdx.x & 31;
    const int ntile = blockIdx.y;
    const int cnt   = g_counts[e];
    if (mtile * 128 >= cnt) return;

    const int tid  = threadIdx.x;
    const int wid  = tid >> 5;
    const int lane = tid & 31;

    const uint32_t sb = smem_u32(smem);
    const fp16* ath = g_acth + (size_t)e * TOKS * INTD;
    const fp16* wdh = g_wdh + ((size_t)e * HID + (size_t)ntile * 128) * INTD;

    const uint32_t mloc = (lane & 7) | (((lane >> 3) & 1) << 3);
    const uint32_t csel = lane >> 4;
    const uint32_t wm = (wid & 1) * 64;
    const uint32_t wn = (wid >> 1) * 32;
    uint32_t aoff[4];
#pragma unroll
    for (int mt = 0; mt < 4; mt++) {
        uint32_t r = wm + mt * 16 + mloc;
        aoff[mt] = r * 64 + ((csel ^ ((r >> 1) & 3)) << 4);
    }
    uint32_t boff[2];
#pragma unroll
    for (int i = 0; i < 2; i++) {
        uint32_t r = wn + i * 16 + mloc;
        boff[i] = r * 64 + ((csel ^ ((r >> 1) & 3)) << 4);
    }

    float cd[4][4][4] = {};

    auto load_stage = [&](int stage, int kc) {
        const uint32_t st = sb + stage * STAGE_BYTES;
        const int k0 = kc * 32;
#pragma unroll
        for (int i = 0; i < 4; i++) {
            int q   = tid + i * 256;
            int buf = q >> 9;
            int rc  = q & 511;
            int row = rc >> 2;
            int ch  = rc & 3;
            uint32_t dst = st + buf * 8192 + row * 64 + ((ch ^ ((row >> 1) & 3)) << 4);
            const fp16* src;
            if (buf == 0) {
                int rp = mtile * 128 + row;
                src = ath + (size_t)(rp < cnt ? rp : cnt - 1) * INTD + k0 + ch * 8;
            } else {
                src = wdh + (size_t)row * INTD + k0 + ch * 8;
            }
            CPA(dst, src);
        }
    };

    load_stage(0, 0); CPC();
    load_stage(1, 1); CPC();

    for (int kc = 0; kc < INTD / 32; kc++) {
        const int stage = kc % 3;
        if (kc + 2 < INTD / 32) load_stage((kc + 2) % 3, kc + 2);
        CPC();
        CPW2();
        __syncthreads();

        const uint32_t sA = sb + stage * STAGE_BYTES;
        const uint32_t sB = sA + 8192;
#pragma unroll
        for (int ksx = 0; ksx < 64; ksx += 32) {
            uint32_t ah[4][4], dh[8];
#pragma unroll
            for (int mt = 0; mt < 4; mt++) LDM4(ah[mt], sA + (aoff[mt] ^ ksx));
            LDM4(dh,     sB + (boff[0] ^ ksx));
            LDM4(dh + 4, sB + (boff[1] ^ ksx));
#pragma unroll
            for (int mt = 0; mt < 4; mt++)
#pragma unroll
                for (int nt = 0; nt < 4; nt++) {
                    int b0 = (nt >> 1) * 4 + (nt & 1);
                    MMA(cd[mt][nt], ah[mt], dh[b0], dh[b0 + 2]);
                }
        }
        __syncthreads();
    }

    // epilogue: scale by routing weight, atomicAdd into out (2 commutative adds/elem)
#pragma unroll
    for (int mt = 0; mt < 4; mt++) {
        int p0 = mtile * 128 + wm + mt * 16 + (lane >> 2);
        int p1 = p0 + 8;
        bool v0 = p0 < cnt, v1 = p1 < cnt;
        float w0 = 0.f, w1 = 0.f;
        float *o0 = out, *o1 = out;
        if (v0) {
            w0 = g_wt[e * TOKS + p0];
            o0 = out + (size_t)g_tok[e * TOKS + p0] * HID + ntile * 128;
        }
        if (v1) {
            w1 = g_wt[e * TOKS + p1];
            o1 = out + (size_t)g_tok[e * TOKS + p1] * HID + ntile * 128;
        }
#pragma unroll
        for (int nt = 0; nt < 4; nt++) {
            int col = wn + nt * 8 + (lane & 3) * 2;
            if (v0) {
                atomicAdd(o0 + col,     w0 * cd[mt][nt][0]);
                atomicAdd(o0 + col + 1, w0 * cd[mt][nt][1]);
            }
            if (v1) {
                atomicAdd(o1 + col,     w1 * cd[mt][nt][2]);
                atomicAdd(o1 + col + 1, w1 * cd[mt][nt][3]);
            }
        }
    }
}

// ================= launch =====================================================
extern "C" void kernel_launch(void* const* d_in, const int* in_sizes, int n_in,
                              void* d_out, int out_size) {
    const float* x  = (const float*)d_in[0];
    const float* gw = (const float*)d_in[1];
    const float* wg = (const float*)d_in[2];
    const float* wu = (const float*)d_in[3];
    const float* wd = (const float*)d_in[4];
    float* out = (float*)d_out;

    fp16 *xsh, *wgh, *wuh, *wdh;
    cudaGetSymbolAddress((void**)&xsh, g_xsh);
    cudaGetSymbolAddress((void**)&wgh, g_wgh);
    cudaGetSymbolAddress((void**)&wuh, g_wuh);
    cudaGetSymbolAddress((void**)&wdh, g_wdh);

    const int SMEM = SMEM_MAIN + 1024;
    cudaFuncSetAttribute(k2_gateup, cudaFuncAttributeMaxDynamicSharedMemorySize, SMEM);
    cudaFuncSetAttribute(k3_down,   cudaFuncAttributeMaxDynamicSharedMemorySize, SMEM);

    const int NW = NE * INTD * HID / 4;   // weight float4 count
    const int NX = TOKS * HID / 4;

    k_zero <<<(TOKS * HID / 4 + 255) / 256, 256>>>((float4*)out, TOKS * HID / 4);
    k_split_h<<<(NX + 255) / 256, 256>>>((const float4*)x,  xsh, NX);
    k_split_h<<<(NW + 255) / 256, 256>>>((const float4*)wg, wgh, NW);
    k_split_h<<<(NW + 255) / 256, 256>>>((const float4*)wu, wuh, NW);
    k_split_h<<<(NW + 255) / 256, 256>>>((const float4*)wd, wdh, NW);
    k_router<<<TOKS / 8, 256>>>(x, gw);
    k2_gateup<<<dim3(NE * 32, INTD / 64), 256, SMEM>>>();
    k3_down  <<<dim3(NE * 32, HID / 128), 256, SMEM>>>(out);
}

// round 6
// speedup vs baseline: 2.6807x; 1.0344x over previous
#include <cuda_runtime.h>
#include <cuda_fp16.h>
#include <cstdint>

#define TOKS 4096
#define HID  2048
#define INTD 1024
#define NE   8

typedef __half fp16;

// ---------------- persistent device scratch ----------------------------------
__device__ int   g_counts[NE];
__device__ int   g_tok [NE * TOKS];
__device__ float g_wt  [NE * TOKS];
__device__ fp16  g_xsh [TOKS * HID];
__device__ fp16  g_wgh [NE * INTD * HID];
__device__ fp16  g_wuh [NE * INTD * HID];
__device__ fp16  g_wdh [NE * HID * INTD];
__device__ fp16  g_acth[(size_t)NE * TOKS * INTD];

// ---------------- asm helpers -------------------------------------------------
__device__ __forceinline__ uint32_t smem_u32(const void* p) {
    return (uint32_t)__cvta_generic_to_shared(p);
}

#define CPA(s, g)  asm volatile("cp.async.cg.shared.global [%0], [%1], 16;" :: "r"(s), "l"(g))
#define CPC()      asm volatile("cp.async.commit_group;" ::: "memory")
#define CPW2()     asm volatile("cp.async.wait_group 2;" ::: "memory")

#define LDM4(r, addr)                                                           \
    asm volatile("ldmatrix.sync.aligned.m8n8.x4.shared.b16 {%0,%1,%2,%3}, [%4];" \
        : "=r"((r)[0]), "=r"((r)[1]), "=r"((r)[2]), "=r"((r)[3]) : "r"(addr))

#define MMA(c, a, b0, b1)                                                       \
    asm volatile("mma.sync.aligned.m16n8k16.row.col.f32.f16.f16.f32 "            \
        "{%0,%1,%2,%3},{%4,%5,%6,%7},{%8,%9},{%0,%1,%2,%3};"                     \
        : "+f"((c)[0]), "+f"((c)[1]), "+f"((c)[2]), "+f"((c)[3])                 \
        : "r"((a)[0]), "r"((a)[1]), "r"((a)[2]), "r"((a)[3]), "r"(b0), "r"(b1))

// ================= kernel: zero out + counts ==================================
__global__ void __launch_bounds__(256) k_zero(float4* __restrict__ out, int n4) {
    int i = blockIdx.x * 256 + threadIdx.x;
    if (i < n4) out[i] = make_float4(0.f, 0.f, 0.f, 0.f);
    if (blockIdx.x == 0 && threadIdx.x < NE) g_counts[threadIdx.x] = 0;
}

// ================= kernel: fused fp32 -> fp16 conversion (x + 3 weights) ======
// region layout in float4 units: x[0,2M) wg[2M,6M) wu[6M,10M) wd[10M,14M)
#define R_X  (TOKS * HID / 4)
#define R_W  (NE * INTD * HID / 4)
__global__ void __launch_bounds__(256)
k_cvt_all(const float4* __restrict__ x,  const float4* __restrict__ wg,
          const float4* __restrict__ wu, const float4* __restrict__ wd) {
    int base = (blockIdx.x * 256 + threadIdx.x) * 2;   // 2 float4 per thread
    const float4* src;
    __half2* dst;
    int local;
    if (base < R_X)                { src = x;  dst = (__half2*)g_xsh; local = base; }
    else if (base < R_X + R_W)     { src = wg; dst = (__half2*)g_wgh; local = base - R_X; }
    else if (base < R_X + 2 * R_W) { src = wu; dst = (__half2*)g_wuh; local = base - R_X - R_W; }
    else                           { src = wd; dst = (__half2*)g_wdh; local = base - R_X - 2 * R_W; }
#pragma unroll
    for (int j = 0; j < 2; j++) {
        float4 v = src[local + j];
        __half2 hp0, hp1;
        hp0.x = __float2half_rn(v.x); hp0.y = __float2half_rn(v.y);
        hp1.x = __float2half_rn(v.z); hp1.y = __float2half_rn(v.w);
        dst[(local + j) * 2]     = hp0;
        dst[(local + j) * 2 + 1] = hp1;
    }
}

// ================= kernel: router (warp per token) ============================
__global__ void __launch_bounds__(256) k_router(const float* __restrict__ x,
                                                const float* __restrict__ gw) {
    int t    = blockIdx.x * 8 + (threadIdx.x >> 5);
    int lane = threadIdx.x & 31;
    if (t >= TOKS) return;
    const float* h = x + (size_t)t * HID;

    float acc[NE];
#pragma unroll
    for (int e = 0; e < NE; e++) acc[e] = 0.0f;
    for (int i = lane; i < HID; i += 32) {
        float hv = h[i];
#pragma unroll
        for (int e = 0; e < NE; e++) acc[e] += hv * gw[e * HID + i];
    }
#pragma unroll
    for (int e = 0; e < NE; e++)
#pragma unroll
        for (int o = 16; o; o >>= 1) acc[e] += __shfl_xor_sync(0xFFFFFFFFu, acc[e], o);

    if (lane == 0) {
        float mx = acc[0];
#pragma unroll
        for (int e = 1; e < NE; e++) mx = fmaxf(mx, acc[e]);
        float p[NE], s = 0.0f;
#pragma unroll
        for (int e = 0; e < NE; e++) { p[e] = expf(acc[e] - mx); s += p[e]; }
#pragma unroll
        for (int e = 0; e < NE; e++) p[e] /= s;

        int i1 = 0;
#pragma unroll
        for (int e = 1; e < NE; e++) if (p[e] > p[i1]) i1 = e;
        int i2 = (i1 == 0) ? 1 : 0;
#pragma unroll
        for (int e = 0; e < NE; e++) if (e != i1 && p[e] > p[i2]) i2 = e;

        float denom = p[i1] + p[i2];
        int pos = atomicAdd(&g_counts[i1], 1);
        g_tok[i1 * TOKS + pos] = t;
        g_wt [i1 * TOKS + pos] = p[i1] / denom;
        pos = atomicAdd(&g_counts[i2], 1);
        g_tok[i2 * TOKS + pos] = t;
        g_wt [i2 * TOKS + pos] = p[i2] / denom;
    }
}

// ================= kernel: gate+up GEMM + SiLU ================================
// tiles: M=128 tokens, N=64 inter cols (gate AND up), K=HID, BK=32
// stage (16KB): [A 8K][B 8K: gate rows 0-63, up rows 64-127]
#define STAGE_BYTES 16384
#define SMEM_MAIN   (3 * STAGE_BYTES)

__global__ void __launch_bounds__(256, 2)
k2_gateup() {
    extern __shared__ char smem[];
    const int e     = blockIdx.x >> 5;
    const int mtile = blockIdx.x & 31;
    const int ntile = blockIdx.y;
    const int cnt   = g_counts[e];
    if (mtile * 128 >= cnt) return;

    const int tid  = threadIdx.x;
    const int wid  = tid >> 5;
    const int lane = tid & 31;

    int* STOK = (int*)(smem + SMEM_MAIN);
    if (tid < 128) {
        int rp = mtile * 128 + tid;
        STOK[tid] = g_tok[e * TOKS + (rp < cnt ? rp : cnt - 1)];
    }
    __syncthreads();

    const uint32_t sb = smem_u32(smem);
    const fp16* wgh = g_wgh + ((size_t)e * INTD + (size_t)ntile * 64) * HID;
    const fp16* wuh = g_wuh + ((size_t)e * INTD + (size_t)ntile * 64) * HID;

    const uint32_t mloc = (lane & 7) | (((lane >> 3) & 1) << 3);
    const uint32_t csel = lane >> 4;
    const uint32_t wm = (wid & 1) * 64;
    const uint32_t wn = (wid >> 1) * 16;
    uint32_t aoff[4];
#pragma unroll
    for (int mt = 0; mt < 4; mt++) {
        uint32_t r = wm + mt * 16 + mloc;
        aoff[mt] = r * 64 + ((csel ^ ((r >> 1) & 3)) << 4);
    }
    const uint32_t brow = wn + mloc;
    const uint32_t boff = brow * 64 + ((csel ^ ((brow >> 1) & 3)) << 4);

    float cg[4][2][4] = {};
    float cu[4][2][4] = {};

    auto load_stage = [&](int stage, int kc) {
        const uint32_t st = sb + stage * STAGE_BYTES;
        const int k0 = kc * 32;
#pragma unroll
        for (int i = 0; i < 4; i++) {
            int q   = tid + i * 256;
            int buf = q >> 9;
            int rc  = q & 511;
            int row = rc >> 2;
            int ch  = rc & 3;
            uint32_t dst = st + buf * 8192 + row * 64 + ((ch ^ ((row >> 1) & 3)) << 4);
            const fp16* src;
            if (buf == 0) src = g_xsh + (size_t)STOK[row] * HID + k0 + ch * 8;
            else          src = (row < 64 ? wgh + (size_t)row * HID
                                          : wuh + (size_t)(row - 64) * HID) + k0 + ch * 8;
            CPA(dst, src);
        }
    };

    load_stage(0, 0); CPC();
    load_stage(1, 1); CPC();

    for (int kc = 0; kc < HID / 32; kc++) {
        const int stage = kc % 3;
        if (kc + 2 < HID / 32) load_stage((kc + 2) % 3, kc + 2);
        CPC();
        CPW2();
        __syncthreads();

        const uint32_t sA = sb + stage * STAGE_BYTES;
        const uint32_t sB = sA + 8192;
#pragma unroll
        for (int ksx = 0; ksx < 64; ksx += 32) {
            uint32_t ah[4][4], gh[4], uh[4];
#pragma unroll
            for (int mt = 0; mt < 4; mt++) LDM4(ah[mt], sA + (aoff[mt] ^ ksx));
            LDM4(gh, sB + (boff ^ ksx));
            LDM4(uh, sB + 4096 + (boff ^ ksx));
#pragma unroll
            for (int mt = 0; mt < 4; mt++)
#pragma unroll
                for (int nt = 0; nt < 2; nt++) {
                    MMA(cg[mt][nt], ah[mt], gh[nt], gh[nt + 2]);
                    MMA(cu[mt][nt], ah[mt], uh[nt], uh[nt + 2]);
                }
        }
        __syncthreads();
    }

    // epilogue: SiLU(g)*u -> fp16 act scratch
#pragma unroll
    for (int mt = 0; mt < 4; mt++) {
        int p0 = mtile * 128 + wm + mt * 16 + (lane >> 2);
        int p1 = p0 + 8;
#pragma unroll
        for (int nt = 0; nt < 2; nt++) {
            int col = ntile * 64 + wn + nt * 8 + (lane & 3) * 2;
            float a0, a1, a2, a3, gv, uv;
            gv = cg[mt][nt][0]; uv = cu[mt][nt][0]; a0 = gv / (1.f + expf(-gv)) * uv;
            gv = cg[mt][nt][1]; uv = cu[mt][nt][1]; a1 = gv / (1.f + expf(-gv)) * uv;
            gv = cg[mt][nt][2]; uv = cu[mt][nt][2]; a2 = gv / (1.f + expf(-gv)) * uv;
            gv = cg[mt][nt][3]; uv = cu[mt][nt][3]; a3 = gv / (1.f + expf(-gv)) * uv;
            if (p0 < cnt) {
                size_t idx = ((size_t)e * TOKS + p0) * INTD + col;
                __half2 hp;
                hp.x = __float2half_rn(a0); hp.y = __float2half_rn(a1);
                *(__half2*)(g_acth + idx) = hp;
            }
            if (p1 < cnt) {
                size_t idx = ((size_t)e * TOKS + p1) * INTD + col;
                __half2 hp;
                hp.x = __float2half_rn(a2); hp.y = __float2half_rn(a3);
                *(__half2*)(g_acth + idx) = hp;
            }
        }
    }
}

// ================= kernel: down GEMM + weighted scatter-add ===================
// tiles: M=128 slot rows, N=128 hid cols, K=INTD, BK=32
// stage (16KB): [A 8K][W 8K]
__global__ void __launch_bounds__(256, 2)
k3_down(float* __restrict__ out) {
    extern __shared__ char smem[];
    const int e     = blockIdx.x >> 5;
    const int mtile = blockIdx.x & 31;
    const int ntile = blockIdx.y;
    const int cnt   = g_counts[e];
    if (mtile * 128 >= cnt) return;

    const int tid  = threadIdx.x;
    const int wid  = tid >> 5;
    const int lane = tid & 31;

    const uint32_t sb = smem_u32(smem);
    const fp16* ath = g_acth + (size_t)e * TOKS * INTD;
    const fp16* wdh = g_wdh + ((size_t)e * HID + (size_t)ntile * 128) * INTD;

    const uint32_t mloc = (lane & 7) | (((lane >> 3) & 1) << 3);
    const uint32_t csel = lane >> 4;
    const uint32_t wm = (wid & 1) * 64;
    const uint32_t wn = (wid >> 1) * 32;
    uint32_t aoff[4];
#pragma unroll
    for (int mt = 0; mt < 4; mt++) {
        uint32_t r = wm + mt * 16 + mloc;
        aoff[mt] = r * 64 + ((csel ^ ((r >> 1) & 3)) << 4);
    }
    uint32_t boff[2];
#pragma unroll
    for (int i = 0; i < 2; i++) {
        uint32_t r = wn + i * 16 + mloc;
        boff[i] = r * 64 + ((csel ^ ((r >> 1) & 3)) << 4);
    }

    float cd[4][4][4] = {};

    auto load_stage = [&](int stage, int kc) {
        const uint32_t st = sb + stage * STAGE_BYTES;
        const int k0 = kc * 32;
#pragma unroll
        for (int i = 0; i < 4; i++) {
            int q   = tid + i * 256;
            int buf = q >> 9;
            int rc  = q & 511;
            int row = rc >> 2;
            int ch  = rc & 3;
            uint32_t dst = st + buf * 8192 + row * 64 + ((ch ^ ((row >> 1) & 3)) << 4);
            const fp16* src;
            if (buf == 0) {
                int rp = mtile * 128 + row;
                src = ath + (size_t)(rp < cnt ? rp : cnt - 1) * INTD + k0 + ch * 8;
            } else {
                src = wdh + (size_t)row * INTD + k0 + ch * 8;
            }
            CPA(dst, src);
        }
    };

    load_stage(0, 0); CPC();
    load_stage(1, 1); CPC();

    for (int kc = 0; kc < INTD / 32; kc++) {
        const int stage = kc % 3;
        if (kc + 2 < INTD / 32) load_stage((kc + 2) % 3, kc + 2);
        CPC();
        CPW2();
        __syncthreads();

        const uint32_t sA = sb + stage * STAGE_BYTES;
        const uint32_t sB = sA + 8192;
#pragma unroll
        for (int ksx = 0; ksx < 64; ksx += 32) {
            uint32_t ah[4][4], dh[8];
#pragma unroll
            for (int mt = 0; mt < 4; mt++) LDM4(ah[mt], sA + (aoff[mt] ^ ksx));
            LDM4(dh,     sB + (boff[0] ^ ksx));
            LDM4(dh + 4, sB + (boff[1] ^ ksx));
#pragma unroll
            for (int mt = 0; mt < 4; mt++)
#pragma unroll
                for (int nt = 0; nt < 4; nt++) {
                    int b0 = (nt >> 1) * 4 + (nt & 1);
                    MMA(cd[mt][nt], ah[mt], dh[b0], dh[b0 + 2]);
                }
        }
        __syncthreads();
    }

    // epilogue: scale by routing weight, atomicAdd into out (2 commutative adds/elem)
#pragma unroll
    for (int mt = 0; mt < 4; mt++) {
        int p0 = mtile * 128 + wm + mt * 16 + (lane >> 2);
        int p1 = p0 + 8;
        bool v0 = p0 < cnt, v1 = p1 < cnt;
        float w0 = 0.f, w1 = 0.f;
        float *o0 = out, *o1 = out;
        if (v0) {
            w0 = g_wt[e * TOKS + p0];
            o0 = out + (size_t)g_tok[e * TOKS + p0] * HID + ntile * 128;
        }
        if (v1) {
            w1 = g_wt[e * TOKS + p1];
            o1 = out + (size_t)g_tok[e * TOKS + p1] * HID + ntile * 128;
        }
#pragma unroll
        for (int nt = 0; nt < 4; nt++) {
            int col = wn + nt * 8 + (lane & 3) * 2;
            if (v0) {
                atomicAdd(o0 + col,     w0 * cd[mt][nt][0]);
                atomicAdd(o0 + col + 1, w0 * cd[mt][nt][1]);
            }
            if (v1) {
                atomicAdd(o1 + col,     w1 * cd[mt][nt][2]);
                atomicAdd(o1 + col + 1, w1 * cd[mt][nt][3]);
            }
        }
    }
}

// ================= launch =====================================================
extern "C" void kernel_launch(void* const* d_in, const int* in_sizes, int n_in,
                              void* d_out, int out_size) {
    const float* x  = (const float*)d_in[0];
    const float* gw = (const float*)d_in[1];
    const float* wg = (const float*)d_in[2];
    const float* wu = (const float*)d_in[3];
    const float* wd = (const float*)d_in[4];
    float* out = (float*)d_out;

    const int SMEM = SMEM_MAIN + 1024;
    cudaFuncSetAttribute(k2_gateup, cudaFuncAttributeMaxDynamicSharedMemorySize, SMEM);
    cudaFuncSetAttribute(k3_down,   cudaFuncAttributeMaxDynamicSharedMemorySize, SMEM);

    const int NCVT = (R_X + 3 * R_W) / 2;   // threads, 2 float4 each

    k_zero   <<<(TOKS * HID / 4 + 255) / 256, 256>>>((float4*)out, TOKS * HID / 4);
    k_router <<<TOKS / 8, 256>>>(x, gw);
    k_cvt_all<<<(NCVT + 255) / 256, 256>>>((const float4*)x, (const float4*)wg,
                                           (const float4*)wu, (const float4*)wd);
    k2_gateup<<<dim3(NE * 32, INTD / 64), 256, SMEM>>>();
    k3_down  <<<dim3(NE * 32, HID / 128), 256, SMEM>>>(out);
}

// round 7
// speedup vs baseline: 2.9016x; 1.0824x over previous
#include <cuda_runtime.h>
#include <cuda_fp16.h>
#include <cstdint>

#define TOKS 4096
#define HID  2048
#define INTD 1024
#define NE   8

typedef __half fp16;

// ---------------- persistent device scratch ----------------------------------
__device__ int   g_counts[NE];
__device__ int   g_tok [NE * TOKS];
__device__ float g_wt  [NE * TOKS];
__device__ fp16  g_xsh [TOKS * HID];
__device__ fp16  g_wgh [NE * INTD * HID];
__device__ fp16  g_wuh [NE * INTD * HID];
__device__ fp16  g_wdh [NE * HID * INTD];
__device__ fp16  g_acth[(size_t)NE * TOKS * INTD];

// ---------------- asm helpers -------------------------------------------------
__device__ __forceinline__ uint32_t smem_u32(const void* p) {
    return (uint32_t)__cvta_generic_to_shared(p);
}

#define CPA(s, g)  asm volatile("cp.async.cg.shared.global [%0], [%1], 16;" :: "r"(s), "l"(g))
#define CPC()      asm volatile("cp.async.commit_group;" ::: "memory")
#define CPW(n)     asm volatile("cp.async.wait_group %0;" :: "n"(n) : "memory")

#define LDM4(r, addr)                                                           \
    asm volatile("ldmatrix.sync.aligned.m8n8.x4.shared.b16 {%0,%1,%2,%3}, [%4];" \
        : "=r"((r)[0]), "=r"((r)[1]), "=r"((r)[2]), "=r"((r)[3]) : "r"(addr))

#define MMA(c, a, b0, b1)                                                       \
    asm volatile("mma.sync.aligned.m16n8k16.row.col.f32.f16.f16.f32 "            \
        "{%0,%1,%2,%3},{%4,%5,%6,%7},{%8,%9},{%0,%1,%2,%3};"                     \
        : "+f"((c)[0]), "+f"((c)[1]), "+f"((c)[2]), "+f"((c)[3])                 \
        : "r"((a)[0]), "r"((a)[1]), "r"((a)[2]), "r"((a)[3]), "r"(b0), "r"(b1))

// ================= kernel: zero out + counts ==================================
__global__ void __launch_bounds__(256) k_zero(float4* __restrict__ out, int n4) {
    int i = blockIdx.x * 256 + threadIdx.x;
    if (i < n4) out[i] = make_float4(0.f, 0.f, 0.f, 0.f);
    if (blockIdx.x == 0 && threadIdx.x < NE) g_counts[threadIdx.x] = 0;
}

// ================= kernel: fused fp32 -> fp16 conversion (x + 3 weights) ======
#define R_X  (TOKS * HID / 4)
#define R_W  (NE * INTD * HID / 4)
__global__ void __launch_bounds__(256)
k_cvt_all(const float4* __restrict__ x,  const float4* __restrict__ wg,
          const float4* __restrict__ wu, const float4* __restrict__ wd) {
    int base = (blockIdx.x * 256 + threadIdx.x) * 2;
    const float4* src;
    __half2* dst;
    int local;
    if (base < R_X)                { src = x;  dst = (__half2*)g_xsh; local = base; }
    else if (base < R_X + R_W)     { src = wg; dst = (__half2*)g_wgh; local = base - R_X; }
    else if (base < R_X + 2 * R_W) { src = wu; dst = (__half2*)g_wuh; local = base - R_X - R_W; }
    else                           { src = wd; dst = (__half2*)g_wdh; local = base - R_X - 2 * R_W; }
#pragma unroll
    for (int j = 0; j < 2; j++) {
        float4 v = src[local + j];
        __half2 hp0, hp1;
        hp0.x = __float2half_rn(v.x); hp0.y = __float2half_rn(v.y);
        hp1.x = __float2half_rn(v.z); hp1.y = __float2half_rn(v.w);
        dst[(local + j) * 2]     = hp0;
        dst[(local + j) * 2 + 1] = hp1;
    }
}

// ================= kernel: router (warp per token) ============================
__global__ void __launch_bounds__(256) k_router(const float* __restrict__ x,
                                                const float* __restrict__ gw) {
    int t    = blockIdx.x * 8 + (threadIdx.x >> 5);
    int lane = threadIdx.x & 31;
    if (t >= TOKS) return;
    const float* h = x + (size_t)t * HID;

    float acc[NE];
#pragma unroll
    for (int e = 0; e < NE; e++) acc[e] = 0.0f;
    for (int i = lane; i < HID; i += 32) {
        float hv = h[i];
#pragma unroll
        for (int e = 0; e < NE; e++) acc[e] += hv * gw[e * HID + i];
    }
#pragma unroll
    for (int e = 0; e < NE; e++)
#pragma unroll
        for (int o = 16; o; o >>= 1) acc[e] += __shfl_xor_sync(0xFFFFFFFFu, acc[e], o);

    if (lane == 0) {
        float mx = acc[0];
#pragma unroll
        for (int e = 1; e < NE; e++) mx = fmaxf(mx, acc[e]);
        float p[NE], s = 0.0f;
#pragma unroll
        for (int e = 0; e < NE; e++) { p[e] = expf(acc[e] - mx); s += p[e]; }
#pragma unroll
        for (int e = 0; e < NE; e++) p[e] /= s;

        int i1 = 0;
#pragma unroll
        for (int e = 1; e < NE; e++) if (p[e] > p[i1]) i1 = e;
        int i2 = (i1 == 0) ? 1 : 0;
#pragma unroll
        for (int e = 0; e < NE; e++) if (e != i1 && p[e] > p[i2]) i2 = e;

        float denom = p[i1] + p[i2];
        int pos = atomicAdd(&g_counts[i1], 1);
        g_tok[i1 * TOKS + pos] = t;
        g_wt [i1 * TOKS + pos] = p[i1] / denom;
        pos = atomicAdd(&g_counts[i2], 1);
        g_tok[i2 * TOKS + pos] = t;
        g_wt [i2 * TOKS + pos] = p[i2] / denom;
    }
}

// ================= kernel: gate+up GEMM + SiLU ================================
// M=128 tokens, N=64 inter cols (gate AND up), K=HID, BK=32, 4-stage cp.async
// stage (16KB): [A 8K][B 8K: gate rows 0-63, up rows 64-127]
#define STAGE_BYTES 16384
#define NSTAGE 4
#define SMEM_MAIN (NSTAGE * STAGE_BYTES)

__global__ void __launch_bounds__(256, 2)
k2_gateup() {
    extern __shared__ char smem[];
    const int e     = blockIdx.x >> 5;
    const int mtile = blockIdx.x & 31;
    const int ntile = blockIdx.y;
    const int cnt   = g_counts[e];
    if (mtile * 128 >= cnt) return;

    const int tid  = threadIdx.x;
    const int wid  = tid >> 5;
    const int lane = tid & 31;

    int* STOK = (int*)(smem + SMEM_MAIN);
    if (tid < 128) {
        int rp = mtile * 128 + tid;
        STOK[tid] = g_tok[e * TOKS + (rp < cnt ? rp : cnt - 1)];
    }
    __syncthreads();

    const uint32_t sb = smem_u32(smem);
    const fp16* wgh = g_wgh + ((size_t)e * INTD + (size_t)ntile * 64) * HID;
    const fp16* wuh = g_wuh + ((size_t)e * INTD + (size_t)ntile * 64) * HID;

    // precomputed cp.async addressing (loop-invariant)
    const fp16* srcrow[4];
    uint32_t    dstoff[4];
#pragma unroll
    for (int i = 0; i < 4; i++) {
        int q   = tid + i * 256;
        int buf = q >> 9;
        int rc  = q & 511;
        int row = rc >> 2;
        int ch  = rc & 3;
        dstoff[i] = buf * 8192 + row * 64 + ((ch ^ ((row >> 1) & 3)) << 4);
        if (buf == 0) srcrow[i] = g_xsh + (size_t)STOK[row] * HID + ch * 8;
        else          srcrow[i] = (row < 64 ? wgh + (size_t)row * HID
                                            : wuh + (size_t)(row - 64) * HID) + ch * 8;
    }

    const uint32_t mloc = (lane & 7) | (((lane >> 3) & 1) << 3);
    const uint32_t csel = lane >> 4;
    const uint32_t wm = (wid & 1) * 64;
    const uint32_t wn = (wid >> 1) * 16;
    uint32_t aoff[4];
#pragma unroll
    for (int mt = 0; mt < 4; mt++) {
        uint32_t r = wm + mt * 16 + mloc;
        aoff[mt] = r * 64 + ((csel ^ ((r >> 1) & 3)) << 4);
    }
    const uint32_t brow = wn + mloc;
    const uint32_t boff = brow * 64 + ((csel ^ ((brow >> 1) & 3)) << 4);

    float cg[4][2][4] = {};
    float cu[4][2][4] = {};

    auto load_stage = [&](int stage, int kc) {
        const uint32_t st = sb + stage * STAGE_BYTES;
        const int k0 = kc * 32;
#pragma unroll
        for (int i = 0; i < 4; i++) CPA(st + dstoff[i], srcrow[i] + k0);
    };

    load_stage(0, 0); CPC();
    load_stage(1, 1); CPC();
    load_stage(2, 2); CPC();

    const int NC = HID / 32;
    for (int kc = 0; kc < NC; kc++) {
        CPW(2);             // own copies for stage kc complete
        __syncthreads();    // publish stage kc; readers of stage (kc-1) done
        if (kc + 3 < NC) load_stage((kc + 3) & 3, kc + 3);
        CPC();

        const uint32_t sA = sb + (kc & 3) * STAGE_BYTES;
        const uint32_t sB = sA + 8192;
#pragma unroll
        for (int ksx = 0; ksx < 64; ksx += 32) {
            uint32_t ah[4][4], gh[4], uh[4];
#pragma unroll
            for (int mt = 0; mt < 4; mt++) LDM4(ah[mt], sA + (aoff[mt] ^ ksx));
            LDM4(gh, sB + (boff ^ ksx));
            LDM4(uh, sB + 4096 + (boff ^ ksx));
#pragma unroll
            for (int mt = 0; mt < 4; mt++)
#pragma unroll
                for (int nt = 0; nt < 2; nt++) {
                    MMA(cg[mt][nt], ah[mt], gh[nt], gh[nt + 2]);
                    MMA(cu[mt][nt], ah[mt], uh[nt], uh[nt + 2]);
                }
        }
    }

    // epilogue: SiLU(g)*u -> fp16 act scratch
#pragma unroll
    for (int mt = 0; mt < 4; mt++) {
        int p0 = mtile * 128 + wm + mt * 16 + (lane >> 2);
        int p1 = p0 + 8;
#pragma unroll
        for (int nt = 0; nt < 2; nt++) {
            int col = ntile * 64 + wn + nt * 8 + (lane & 3) * 2;
            float a0, a1, a2, a3, gv, uv;
            gv = cg[mt][nt][0]; uv = cu[mt][nt][0]; a0 = gv / (1.f + expf(-gv)) * uv;
            gv = cg[mt][nt][1]; uv = cu[mt][nt][1]; a1 = gv / (1.f + expf(-gv)) * uv;
            gv = cg[mt][nt][2]; uv = cu[mt][nt][2]; a2 = gv / (1.f + expf(-gv)) * uv;
            gv = cg[mt][nt][3]; uv = cu[mt][nt][3]; a3 = gv / (1.f + expf(-gv)) * uv;
            if (p0 < cnt) {
                size_t idx = ((size_t)e * TOKS + p0) * INTD + col;
                __half2 hp;
                hp.x = __float2half_rn(a0); hp.y = __float2half_rn(a1);
                *(__half2*)(g_acth + idx) = hp;
            }
            if (p1 < cnt) {
                size_t idx = ((size_t)e * TOKS + p1) * INTD + col;
                __half2 hp;
                hp.x = __float2half_rn(a2); hp.y = __float2half_rn(a3);
                *(__half2*)(g_acth + idx) = hp;
            }
        }
    }
}

// ================= kernel: down GEMM + weighted scatter-add ===================
// M=128 slot rows, N=128 hid cols, K=INTD, BK=32, 4-stage cp.async
// stage (16KB): [A 8K][W 8K]
__global__ void __launch_bounds__(256, 2)
k3_down(float* __restrict__ out) {
    extern __shared__ char smem[];
    const int e     = blockIdx.x >> 5;
    const int mtile = blockIdx.x & 31;
    const int ntile = blockIdx.y;
    const int cnt   = g_counts[e];
    if (mtile * 128 >= cnt) return;

    const int tid  = threadIdx.x;
    const int wid  = tid >> 5;
    const int lane = tid & 31;

    const uint32_t sb = smem_u32(smem);
    const fp16* ath = g_acth + (size_t)e * TOKS * INTD;
    const fp16* wdh = g_wdh + ((size_t)e * HID + (size_t)ntile * 128) * INTD;

    // precomputed cp.async addressing
    const fp16* srcrow[4];
    uint32_t    dstoff[4];
#pragma unroll
    for (int i = 0; i < 4; i++) {
        int q   = tid + i * 256;
        int buf = q >> 9;
        int rc  = q & 511;
        int row = rc >> 2;
        int ch  = rc & 3;
        dstoff[i] = buf * 8192 + row * 64 + ((ch ^ ((row >> 1) & 3)) << 4);
        if (buf == 0) {
            int rp = mtile * 128 + row;
            srcrow[i] = ath + (size_t)(rp < cnt ? rp : cnt - 1) * INTD + ch * 8;
        } else {
            srcrow[i] = wdh + (size_t)row * INTD + ch * 8;
        }
    }

    const uint32_t mloc = (lane & 7) | (((lane >> 3) & 1) << 3);
    const uint32_t csel = lane >> 4;
    const uint32_t wm = (wid & 1) * 64;
    const uint32_t wn = (wid >> 1) * 32;
    uint32_t aoff[4];
#pragma unroll
    for (int mt = 0; mt < 4; mt++) {
        uint32_t r = wm + mt * 16 + mloc;
        aoff[mt] = r * 64 + ((csel ^ ((r >> 1) & 3)) << 4);
    }
    uint32_t boff[2];
#pragma unroll
    for (int i = 0; i < 2; i++) {
        uint32_t r = wn + i * 16 + mloc;
        boff[i] = r * 64 + ((csel ^ ((r >> 1) & 3)) << 4);
    }

    float cd[4][4][4] = {};

    auto load_stage = [&](int stage, int kc) {
        const uint32_t st = sb + stage * STAGE_BYTES;
        const int k0 = kc * 32;
#pragma unroll
        for (int i = 0; i < 4; i++) CPA(st + dstoff[i], srcrow[i] + k0);
    };

    load_stage(0, 0); CPC();
    load_stage(1, 1); CPC();
    load_stage(2, 2); CPC();

    const int NC = INTD / 32;
    for (int kc = 0; kc < NC; kc++) {
        CPW(2);
        __syncthreads();
        if (kc + 3 < NC) load_stage((kc + 3) & 3, kc + 3);
        CPC();

        const uint32_t sA = sb + (kc & 3) * STAGE_BYTES;
        const uint32_t sB = sA + 8192;
#pragma unroll
        for (int ksx = 0; ksx < 64; ksx += 32) {
            uint32_t ah[4][4], dh[8];
#pragma unroll
            for (int mt = 0; mt < 4; mt++) LDM4(ah[mt], sA + (aoff[mt] ^ ksx));
            LDM4(dh,     sB + (boff[0] ^ ksx));
            LDM4(dh + 4, sB + (boff[1] ^ ksx));
#pragma unroll
            for (int mt = 0; mt < 4; mt++)
#pragma unroll
                for (int nt = 0; nt < 4; nt++) {
                    int b0 = (nt >> 1) * 4 + (nt & 1);
                    MMA(cd[mt][nt], ah[mt], dh[b0], dh[b0 + 2]);
                }
        }
    }

    // epilogue: scale by routing weight, atomicAdd into out
#pragma unroll
    for (int mt = 0; mt < 4; mt++) {
        int p0 = mtile * 128 + wm + mt * 16 + (lane >> 2);
        int p1 = p0 + 8;
        bool v0 = p0 < cnt, v1 = p1 < cnt;
        float w0 = 0.f, w1 = 0.f;
        float *o0 = out, *o1 = out;
        if (v0) {
            w0 = g_wt[e * TOKS + p0];
            o0 = out + (size_t)g_tok[e * TOKS + p0] * HID + ntile * 128;
        }
        if (v1) {
            w1 = g_wt[e * TOKS + p1];
            o1 = out + (size_t)g_tok[e * TOKS + p1] * HID + ntile * 128;
        }
#pragma unroll
        for (int nt = 0; nt < 4; nt++) {
            int col = wn + nt * 8 + (lane & 3) * 2;
            if (v0) {
                atomicAdd(o0 + col,     w0 * cd[mt][nt][0]);
                atomicAdd(o0 + col + 1, w0 * cd[mt][nt][1]);
            }
            if (v1) {
                atomicAdd(o1 + col,     w1 * cd[mt][nt][2]);
                atomicAdd(o1 + col + 1, w1 * cd[mt][nt][3]);
            }
        }
    }
}

// ================= launch =====================================================
extern "C" void kernel_launch(void* const* d_in, const int* in_sizes, int n_in,
                              void* d_out, int out_size) {
    const float* x  = (const float*)d_in[0];
    const float* gw = (const float*)d_in[1];
    const float* wg = (const float*)d_in[2];
    const float* wu = (const float*)d_in[3];
    const float* wd = (const float*)d_in[4];
    float* out = (float*)d_out;

    const int SMEM = SMEM_MAIN + 1024;
    cudaFuncSetAttribute(k2_gateup, cudaFuncAttributeMaxDynamicSharedMemorySize, SMEM);
    cudaFuncSetAttribute(k3_down,   cudaFuncAttributeMaxDynamicSharedMemorySize, SMEM);

    const int NCVT = (R_X + 3 * R_W) / 2;

    k_zero   <<<(TOKS * HID / 4 + 255) / 256, 256>>>((float4*)out, TOKS * HID / 4);
    k_router <<<TOKS / 8, 256>>>(x, gw);
    k_cvt_all<<<(NCVT + 255) / 256, 256>>>((const float4*)x, (const float4*)wg,
                                           (const float4*)wu, (const float4*)wd);
    k2_gateup<<<dim3(NE * 32, INTD / 64), 256, SMEM>>>();
    k3_down  <<<dim3(NE * 32, HID / 128), 256, SMEM>>>(out);
}

// round 8
// speedup vs baseline: 3.0119x; 1.0380x over previous
#include <cuda_runtime.h>
#include <cuda_fp16.h>
#include <cstdint>

#define TOKS 4096
#define HID  2048
#define INTD 1024
#define NE   8

typedef __half fp16;

// ---------------- persistent device scratch ----------------------------------
__device__ int   g_counts[NE];
__device__ int   g_tok [NE * TOKS];
__device__ float g_wt  [NE * TOKS];
__device__ fp16  g_xsh [TOKS * HID];
__device__ fp16  g_wgh [NE * INTD * HID];
__device__ fp16  g_wuh [NE * INTD * HID];
__device__ fp16  g_wdh [NE * HID * INTD];
__device__ fp16  g_acth[(size_t)NE * TOKS * INTD];

// ---------------- asm helpers -------------------------------------------------
__device__ __forceinline__ uint32_t smem_u32(const void* p) {
    return (uint32_t)__cvta_generic_to_shared(p);
}

#define CPA(s, g)  asm volatile("cp.async.cg.shared.global [%0], [%1], 16;" :: "r"(s), "l"(g))
#define CPC()      asm volatile("cp.async.commit_group;" ::: "memory")
#define CPW(n)     asm volatile("cp.async.wait_group %0;" :: "n"(n) : "memory")

#define LDM4(r, addr)                                                           \
    asm volatile("ldmatrix.sync.aligned.m8n8.x4.shared.b16 {%0,%1,%2,%3}, [%4];" \
        : "=r"((r)[0]), "=r"((r)[1]), "=r"((r)[2]), "=r"((r)[3]) : "r"(addr))

#define MMA(c, a, b0, b1)                                                       \
    asm volatile("mma.sync.aligned.m16n8k16.row.col.f32.f16.f16.f32 "            \
        "{%0,%1,%2,%3},{%4,%5,%6,%7},{%8,%9},{%0,%1,%2,%3};"                     \
        : "+f"((c)[0]), "+f"((c)[1]), "+f"((c)[2]), "+f"((c)[3])                 \
        : "r"((a)[0]), "r"((a)[1]), "r"((a)[2]), "r"((a)[3]), "r"(b0), "r"(b1))

// ================= kernel: zero out + counts ==================================
__global__ void __launch_bounds__(256) k_zero(float4* __restrict__ out, int n4) {
    int i = blockIdx.x * 256 + threadIdx.x;
    if (i < n4) out[i] = make_float4(0.f, 0.f, 0.f, 0.f);
    if (blockIdx.x == 0 && threadIdx.x < NE) g_counts[threadIdx.x] = 0;
}

// ================= kernel: fused fp32 -> fp16 conversion (x + 3 weights) ======
#define R_X  (TOKS * HID / 4)
#define R_W  (NE * INTD * HID / 4)
__global__ void __launch_bounds__(256)
k_cvt_all(const float4* __restrict__ x,  const float4* __restrict__ wg,
          const float4* __restrict__ wu, const float4* __restrict__ wd) {
    int base = (blockIdx.x * 256 + threadIdx.x) * 2;
    const float4* src;
    __half2* dst;
    int local;
    if (base < R_X)                { src = x;  dst = (__half2*)g_xsh; local = base; }
    else if (base < R_X + R_W)     { src = wg; dst = (__half2*)g_wgh; local = base - R_X; }
    else if (base < R_X + 2 * R_W) { src = wu; dst = (__half2*)g_wuh; local = base - R_X - R_W; }
    else                           { src = wd; dst = (__half2*)g_wdh; local = base - R_X - 2 * R_W; }
#pragma unroll
    for (int j = 0; j < 2; j++) {
        float4 v = src[local + j];
        __half2 hp0, hp1;
        hp0.x = __float2half_rn(v.x); hp0.y = __float2half_rn(v.y);
        hp1.x = __float2half_rn(v.z); hp1.y = __float2half_rn(v.w);
        dst[(local + j) * 2]     = hp0;
        dst[(local + j) * 2 + 1] = hp1;
    }
}

// ================= kernel: router (warp per token) ============================
__global__ void __launch_bounds__(256) k_router(const float* __restrict__ x,
                                                const float* __restrict__ gw) {
    int t    = blockIdx.x * 8 + (threadIdx.x >> 5);
    int lane = threadIdx.x & 31;
    if (t >= TOKS) return;
    const float* h = x + (size_t)t * HID;

    float acc[NE];
#pragma unroll
    for (int e = 0; e < NE; e++) acc[e] = 0.0f;
    for (int i = lane; i < HID; i += 32) {
        float hv = h[i];
#pragma unroll
        for (int e = 0; e < NE; e++) acc[e] += hv * gw[e * HID + i];
    }
#pragma unroll
    for (int e = 0; e < NE; e++)
#pragma unroll
        for (int o = 16; o; o >>= 1) acc[e] += __shfl_xor_sync(0xFFFFFFFFu, acc[e], o);

    if (lane == 0) {
        float mx = acc[0];
#pragma unroll
        for (int e = 1; e < NE; e++) mx = fmaxf(mx, acc[e]);
        float p[NE], s = 0.0f;
#pragma unroll
        for (int e = 0; e < NE; e++) { p[e] = expf(acc[e] - mx); s += p[e]; }
#pragma unroll
        for (int e = 0; e < NE; e++) p[e] /= s;

        int i1 = 0;
#pragma unroll
        for (int e = 1; e < NE; e++) if (p[e] > p[i1]) i1 = e;
        int i2 = (i1 == 0) ? 1 : 0;
#pragma unroll
        for (int e = 0; e < NE; e++) if (e != i1 && p[e] > p[i2]) i2 = e;

        float denom = p[i1] + p[i2];
        int pos = atomicAdd(&g_counts[i1], 1);
        g_tok[i1 * TOKS + pos] = t;
        g_wt [i1 * TOKS + pos] = p[i1] / denom;
        pos = atomicAdd(&g_counts[i2], 1);
        g_tok[i2 * TOKS + pos] = t;
        g_wt [i2 * TOKS + pos] = p[i2] / denom;
    }
}

// ================= GEMM common: BK=64, 3-stage, 32KB stages ===================
// stage layout: [A 16K: 128 rows x 128B][B 16K: 128 rows x 128B]
// swizzle (128B rows): chunk' = chunk ^ (row & 7);  16B chunks
#define STAGE_BYTES 32768
#define NSTAGE 3
#define SMEM_MAIN (NSTAGE * STAGE_BYTES)

// ================= kernel: gate+up GEMM + SiLU ================================
// M=128 tokens, N=64 inter cols (gate AND up share A), K=HID
__global__ void __launch_bounds__(256, 2)
k2_gateup() {
    extern __shared__ char smem[];
    const int e     = blockIdx.x >> 5;
    const int mtile = blockIdx.x & 31;
    const int ntile = blockIdx.y;
    const int cnt   = g_counts[e];
    if (mtile * 128 >= cnt) return;

    const int tid  = threadIdx.x;
    const int wid  = tid >> 5;
    const int lane = tid & 31;

    int* STOK = (int*)(smem + SMEM_MAIN);
    if (tid < 128) {
        int rp = mtile * 128 + tid;
        STOK[tid] = g_tok[e * TOKS + (rp < cnt ? rp : cnt - 1)];
    }
    __syncthreads();

    const uint32_t sb = smem_u32(smem);
    const fp16* wgh = g_wgh + ((size_t)e * INTD + (size_t)ntile * 64) * HID;
    const fp16* wuh = g_wuh + ((size_t)e * INTD + (size_t)ntile * 64) * HID;

    // cp.async addressing (loop-invariant): 8 x 16B per thread per stage
    const fp16* srcrow[8];
    uint32_t    dstoff[8];
#pragma unroll
    for (int i = 0; i < 8; i++) {
        int slot = tid + i * 256;            // 0..2047
        int buf  = slot >> 10;               // 0=A, 1=B
        int rc   = slot & 1023;
        int row  = rc >> 3;
        int ch   = rc & 7;
        dstoff[i] = buf * 16384 + row * 128 + ((ch ^ (row & 7)) << 4);
        if (buf == 0) srcrow[i] = g_xsh + (size_t)STOK[row] * HID + ch * 8;
        else          srcrow[i] = (row < 64 ? wgh + (size_t)row * HID
                                            : wuh + (size_t)(row - 64) * HID) + ch * 8;
    }

    const uint32_t mloc = (lane & 7) | (((lane >> 3) & 1) << 3);
    const uint32_t csel = lane >> 4;
    const uint32_t wm = (wid & 1) * 64;
    const uint32_t wn = (wid >> 1) * 16;
    uint32_t aoff[4];
#pragma unroll
    for (int mt = 0; mt < 4; mt++) {
        uint32_t r = wm + mt * 16 + mloc;
        aoff[mt] = r * 128 + ((csel ^ (r & 7)) << 4);
    }
    const uint32_t brow = wn + mloc;
    const uint32_t boff = brow * 128 + ((csel ^ (brow & 7)) << 4);

    float cg[4][2][4] = {};
    float cu[4][2][4] = {};

    auto load_stage = [&](int stage, int kc) {
        const uint32_t st = sb + stage * STAGE_BYTES;
        const int k0 = kc * 64;
#pragma unroll
        for (int i = 0; i < 8; i++) CPA(st + dstoff[i], srcrow[i] + k0);
    };

    load_stage(0, 0); CPC();
    load_stage(1, 1); CPC();

    const int NC = HID / 64;
    int stage = 0;
    for (int kc = 0; kc < NC; kc++) {
        CPW(1);             // stage kc complete (kc+1 may be in flight)
        __syncthreads();    // publish stage kc; readers of stage kc-1 done
        if (kc + 2 < NC) {
            int ns = stage + 2; if (ns >= 3) ns -= 3;
            load_stage(ns, kc + 2);
        }
        CPC();

        const uint32_t sA = sb + stage * STAGE_BYTES;
        const uint32_t sB = sA + 16384;
#pragma unroll
        for (int ks = 0; ks < 4; ks++) {
            const uint32_t x = ks << 5;
            uint32_t ah[4][4], gh[4], uh[4];
#pragma unroll
            for (int mt = 0; mt < 4; mt++) LDM4(ah[mt], sA + (aoff[mt] ^ x));
            LDM4(gh, sB + (boff ^ x));
            LDM4(uh, sB + 8192 + (boff ^ x));
#pragma unroll
            for (int mt = 0; mt < 4; mt++)
#pragma unroll
                for (int nt = 0; nt < 2; nt++) {
                    MMA(cg[mt][nt], ah[mt], gh[nt], gh[nt + 2]);
                    MMA(cu[mt][nt], ah[mt], uh[nt], uh[nt + 2]);
                }
        }
        if (++stage >= 3) stage = 0;
    }

    // epilogue: SiLU(g)*u -> fp16 act scratch
#pragma unroll
    for (int mt = 0; mt < 4; mt++) {
        int p0 = mtile * 128 + wm + mt * 16 + (lane >> 2);
        int p1 = p0 + 8;
#pragma unroll
        for (int nt = 0; nt < 2; nt++) {
            int col = ntile * 64 + wn + nt * 8 + (lane & 3) * 2;
            float a0, a1, a2, a3, gv, uv;
            gv = cg[mt][nt][0]; uv = cu[mt][nt][0]; a0 = gv / (1.f + expf(-gv)) * uv;
            gv = cg[mt][nt][1]; uv = cu[mt][nt][1]; a1 = gv / (1.f + expf(-gv)) * uv;
            gv = cg[mt][nt][2]; uv = cu[mt][nt][2]; a2 = gv / (1.f + expf(-gv)) * uv;
            gv = cg[mt][nt][3]; uv = cu[mt][nt][3]; a3 = gv / (1.f + expf(-gv)) * uv;
            if (p0 < cnt) {
                size_t idx = ((size_t)e * TOKS + p0) * INTD + col;
                __half2 hp;
                hp.x = __float2half_rn(a0); hp.y = __float2half_rn(a1);
                *(__half2*)(g_acth + idx) = hp;
            }
            if (p1 < cnt) {
                size_t idx = ((size_t)e * TOKS + p1) * INTD + col;
                __half2 hp;
                hp.x = __float2half_rn(a2); hp.y = __float2half_rn(a3);
                *(__half2*)(g_acth + idx) = hp;
            }
        }
    }
}

// ================= kernel: down GEMM + weighted scatter-add ===================
// M=128 slot rows, N=128 hid cols, K=INTD
__global__ void __launch_bounds__(256, 2)
k3_down(float* __restrict__ out) {
    extern __shared__ char smem[];
    const int e     = blockIdx.x >> 5;
    const int mtile = blockIdx.x & 31;
    const int ntile = blockIdx.y;
    const int cnt   = g_counts[e];
    if (mtile * 128 >= cnt) return;

    const int tid  = threadIdx.x;
    const int wid  = tid >> 5;
    const int lane = tid & 31;

    const uint32_t sb = smem_u32(smem);
    const fp16* ath = g_acth + (size_t)e * TOKS * INTD;
    const fp16* wdh = g_wdh + ((size_t)e * HID + (size_t)ntile * 128) * INTD;

    const fp16* srcrow[8];
    uint32_t    dstoff[8];
#pragma unroll
    for (int i = 0; i < 8; i++) {
        int slot = tid + i * 256;
        int buf  = slot >> 10;
        int rc   = slot & 1023;
        int row  = rc >> 3;
        int ch   = rc & 7;
        dstoff[i] = buf * 16384 + row * 128 + ((ch ^ (row & 7)) << 4);
        if (buf == 0) {
            int rp = mtile * 128 + row;
            srcrow[i] = ath + (size_t)(rp < cnt ? rp : cnt - 1) * INTD + ch * 8;
        } else {
            srcrow[i] = wdh + (size_t)row * INTD + ch * 8;
        }
    }

    const uint32_t mloc = (lane & 7) | (((lane >> 3) & 1) << 3);
    const uint32_t csel = lane >> 4;
    const uint32_t wm = (wid & 1) * 64;
    const uint32_t wn = (wid >> 1) * 32;
    uint32_t aoff[4];
#pragma unroll
    for (int mt = 0; mt < 4; mt++) {
        uint32_t r = wm + mt * 16 + mloc;
        aoff[mt] = r * 128 + ((csel ^ (r & 7)) << 4);
    }
    uint32_t boff[2];
#pragma unroll
    for (int i = 0; i < 2; i++) {
        uint32_t r = wn + i * 16 + mloc;
        boff[i] = r * 128 + ((csel ^ (r & 7)) << 4);
    }

    float cd[4][4][4] = {};

    auto load_stage = [&](int stage, int kc) {
        const uint32_t st = sb + stage * STAGE_BYTES;
        const int k0 = kc * 64;
#pragma unroll
        for (int i = 0; i < 8; i++) CPA(st + dstoff[i], srcrow[i] + k0);
    };

    load_stage(0, 0); CPC();
    load_stage(1, 1); CPC();

    const int NC = INTD / 64;
    int stage = 0;
    for (int kc = 0; kc < NC; kc++) {
        CPW(1);
        __syncthreads();
        if (kc + 2 < NC) {
            int ns = stage + 2; if (ns >= 3) ns -= 3;
            load_stage(ns, kc + 2);
        }
        CPC();

        const uint32_t sA = sb + stage * STAGE_BYTES;
        const uint32_t sB = sA + 16384;
#pragma unroll
        for (int ks = 0; ks < 4; ks++) {
            const uint32_t x = ks << 5;
            uint32_t ah[4][4], dh[8];
#pragma unroll
            for (int mt = 0; mt < 4; mt++) LDM4(ah[mt], sA + (aoff[mt] ^ x));
            LDM4(dh,     sB + (boff[0] ^ x));
            LDM4(dh + 4, sB + (boff[1] ^ x));
#pragma unroll
            for (int mt = 0; mt < 4; mt++)
#pragma unroll
                for (int nt = 0; nt < 4; nt++) {
                    int b0 = (nt >> 1) * 4 + (nt & 1);
                    MMA(cd[mt][nt], ah[mt], dh[b0], dh[b0 + 2]);
                }
        }
        if (++stage >= 3) stage = 0;
    }

    // epilogue: scale by routing weight, atomicAdd into out
#pragma unroll
    for (int mt = 0; mt < 4; mt++) {
        int p0 = mtile * 128 + wm + mt * 16 + (lane >> 2);
        int p1 = p0 + 8;
        bool v0 = p0 < cnt, v1 = p1 < cnt;
        float w0 = 0.f, w1 = 0.f;
        float *o0 = out, *o1 = out;
        if (v0) {
            w0 = g_wt[e * TOKS + p0];
            o0 = out + (size_t)g_tok[e * TOKS + p0] * HID + ntile * 128;
        }
        if (v1) {
            w1 = g_wt[e * TOKS + p1];
            o1 = out + (size_t)g_tok[e * TOKS + p1] * HID + ntile * 128;
        }
#pragma unroll
        for (int nt = 0; nt < 4; nt++) {
            int col = wn + nt * 8 + (lane & 3) * 2;
            if (v0) {
                atomicAdd(o0 + col,     w0 * cd[mt][nt][0]);
                atomicAdd(o0 + col + 1, w0 * cd[mt][nt][1]);
            }
            if (v1) {
                atomicAdd(o1 + col,     w1 * cd[mt][nt][2]);
                atomicAdd(o1 + col + 1, w1 * cd[mt][nt][3]);
            }
        }
    }
}

// ================= launch =====================================================
extern "C" void kernel_launch(void* const* d_in, const int* in_sizes, int n_in,
                              void* d_out, int out_size) {
    const float* x  = (const float*)d_in[0];
    const float* gw = (const float*)d_in[1];
    const float* wg = (const float*)d_in[2];
    const float* wu = (const float*)d_in[3];
    const float* wd = (const float*)d_in[4];
    float* out = (float*)d_out;

    const int SMEM = SMEM_MAIN + 1024;
    cudaFuncSetAttribute(k2_gateup, cudaFuncAttributeMaxDynamicSharedMemorySize, SMEM);
    cudaFuncSetAttribute(k3_down,   cudaFuncAttributeMaxDynamicSharedMemorySize, SMEM);

    const int NCVT = (R_X + 3 * R_W) / 2;

    k_zero   <<<(TOKS * HID / 4 + 255) / 256, 256>>>((float4*)out, TOKS * HID / 4);
    k_router <<<TOKS / 8, 256>>>(x, gw);
    k_cvt_all<<<(NCVT + 255) / 256, 256>>>((const float4*)x, (const float4*)wg,
                                           (const float4*)wu, (const float4*)wd);
    k2_gateup<<<dim3(NE * 32, INTD / 64), 256, SMEM>>>();
    k3_down  <<<dim3(NE * 32, HID / 128), 256, SMEM>>>(out);
}

// round 9
// speedup vs baseline: 3.1382x; 1.0419x over previous
#include <cuda_runtime.h>
#include <cuda_fp16.h>
#include <cstdint>

#define TOKS 4096
#define HID  2048
#define INTD 1024
#define NE   8

typedef __half fp16;

// ---------------- persistent device scratch ----------------------------------
__device__ int   g_counts[NE];
__device__ int   g_tok [NE * TOKS];
__device__ float g_wt  [NE * TOKS];
__device__ fp16  g_xsh [TOKS * HID];
__device__ fp16  g_wgh [NE * INTD * HID];
__device__ fp16  g_wuh [NE * INTD * HID];
__device__ fp16  g_wdh [NE * HID * INTD];
__device__ fp16  g_acth[(size_t)NE * TOKS * INTD];

// ---------------- asm helpers -------------------------------------------------
__device__ __forceinline__ uint32_t smem_u32(const void* p) {
    return (uint32_t)__cvta_generic_to_shared(p);
}

#define CPA(s, g)  asm volatile("cp.async.cg.shared.global [%0], [%1], 16;" :: "r"(s), "l"(g))
#define CPC()      asm volatile("cp.async.commit_group;" ::: "memory")
#define CPW(n)     asm volatile("cp.async.wait_group %0;" :: "n"(n) : "memory")

#define LDM4(r, addr)                                                           \
    asm volatile("ldmatrix.sync.aligned.m8n8.x4.shared.b16 {%0,%1,%2,%3}, [%4];" \
        : "=r"((r)[0]), "=r"((r)[1]), "=r"((r)[2]), "=r"((r)[3]) : "r"(addr))

#define MMA(c, a, b0, b1)                                                       \
    asm volatile("mma.sync.aligned.m16n8k16.row.col.f32.f16.f16.f32 "            \
        "{%0,%1,%2,%3},{%4,%5,%6,%7},{%8,%9},{%0,%1,%2,%3};"                     \
        : "+f"((c)[0]), "+f"((c)[1]), "+f"((c)[2]), "+f"((c)[3])                 \
        : "r"((a)[0]), "r"((a)[1]), "r"((a)[2]), "r"((a)[3]), "r"(b0), "r"(b1))

// ================= kernel: zero out + counts ==================================
__global__ void __launch_bounds__(256) k_zero(float4* __restrict__ out, int n4) {
    int i = blockIdx.x * 256 + threadIdx.x;
    if (i < n4) out[i] = make_float4(0.f, 0.f, 0.f, 0.f);
    if (blockIdx.x == 0 && threadIdx.x < NE) g_counts[threadIdx.x] = 0;
}

// ================= kernel: fused fp32 -> fp16 conversion ======================
#define R_X  (TOKS * HID / 4)
#define R_W  (NE * INTD * HID / 4)
__global__ void __launch_bounds__(256)
k_cvt_all(const float4* __restrict__ x,  const float4* __restrict__ wg,
          const float4* __restrict__ wu, const float4* __restrict__ wd) {
    int base = (blockIdx.x * 256 + threadIdx.x) * 2;
    const float4* src;
    __half2* dst;
    int local;
    if (base < R_X)                { src = x;  dst = (__half2*)g_xsh; local = base; }
    else if (base < R_X + R_W)     { src = wg; dst = (__half2*)g_wgh; local = base - R_X; }
    else if (base < R_X + 2 * R_W) { src = wu; dst = (__half2*)g_wuh; local = base - R_X - R_W; }
    else                           { src = wd; dst = (__half2*)g_wdh; local = base - R_X - 2 * R_W; }
#pragma unroll
    for (int j = 0; j < 2; j++) {
        float4 v = src[local + j];
        __half2 hp0, hp1;
        hp0.x = __float2half_rn(v.x); hp0.y = __float2half_rn(v.y);
        hp1.x = __float2half_rn(v.z); hp1.y = __float2half_rn(v.w);
        dst[(local + j) * 2]     = hp0;
        dst[(local + j) * 2 + 1] = hp1;
    }
}

// ================= kernel: router (warp per token) ============================
__global__ void __launch_bounds__(256) k_router(const float* __restrict__ x,
                                                const float* __restrict__ gw) {
    int t    = blockIdx.x * 8 + (threadIdx.x >> 5);
    int lane = threadIdx.x & 31;
    if (t >= TOKS) return;
    const float* h = x + (size_t)t * HID;

    float acc[NE];
#pragma unroll
    for (int e = 0; e < NE; e++) acc[e] = 0.0f;
    for (int i = lane; i < HID; i += 32) {
        float hv = h[i];
#pragma unroll
        for (int e = 0; e < NE; e++) acc[e] += hv * gw[e * HID + i];
    }
#pragma unroll
    for (int e = 0; e < NE; e++)
#pragma unroll
        for (int o = 16; o; o >>= 1) acc[e] += __shfl_xor_sync(0xFFFFFFFFu, acc[e], o);

    if (lane == 0) {
        float mx = acc[0];
#pragma unroll
        for (int e = 1; e < NE; e++) mx = fmaxf(mx, acc[e]);
        float p[NE], s = 0.0f;
#pragma unroll
        for (int e = 0; e < NE; e++) { p[e] = expf(acc[e] - mx); s += p[e]; }
#pragma unroll
        for (int e = 0; e < NE; e++) p[e] /= s;

        int i1 = 0;
#pragma unroll
        for (int e = 1; e < NE; e++) if (p[e] > p[i1]) i1 = e;
        int i2 = (i1 == 0) ? 1 : 0;
#pragma unroll
        for (int e = 0; e < NE; e++) if (e != i1 && p[e] > p[i2]) i2 = e;

        float denom = p[i1] + p[i2];
        int pos = atomicAdd(&g_counts[i1], 1);
        g_tok[i1 * TOKS + pos] = t;
        g_wt [i1 * TOKS + pos] = p[i1] / denom;
        pos = atomicAdd(&g_counts[i2], 1);
        g_tok[i2 * TOKS + pos] = t;
        g_wt [i2 * TOKS + pos] = p[i2] / denom;
    }
}

// ================= GEMM common: M=64 CTA tiles, BK=64, 3-stage 24KB ===========
// stage layout: [A 8K: 64 rows x 128B][B 16K: 128 rows x 128B]
// swizzle: 16B chunk' = chunk ^ (row & 7)
#define STAGE_BYTES 24576
#define NSTAGE 3
#define SMEM_MAIN (NSTAGE * STAGE_BYTES)

// ================= kernel: gate+up GEMM + SiLU ================================
// CTA tile: M=64 tokens x N=64 inter (gate rows 0-63 + up rows 64-127 in B)
__global__ void __launch_bounds__(256, 3)
k2_gateup() {
    extern __shared__ char smem[];
    const int e     = blockIdx.x >> 6;
    const int mtile = blockIdx.x & 63;
    const int ntile = blockIdx.y;
    const int cnt   = g_counts[e];
    if (mtile * 64 >= cnt) return;

    const int tid  = threadIdx.x;
    const int wid  = tid >> 5;
    const int lane = tid & 31;

    int* STOK = (int*)(smem + SMEM_MAIN);
    if (tid < 64) {
        int rp = mtile * 64 + tid;
        STOK[tid] = g_tok[e * TOKS + (rp < cnt ? rp : cnt - 1)];
    }
    __syncthreads();

    const uint32_t sb = smem_u32(smem);
    const fp16* wghb = g_wgh + ((size_t)e * INTD + (size_t)ntile * 64) * HID;
    const fp16* wuhb = g_wuh + ((size_t)e * INTD + (size_t)ntile * 64) * HID;

    // cp.async: 6 x 16B per thread per stage. slot = tid + i*256.
    // i=0,1 -> A rows (tid>>3)+32i ; i=2,3 -> gate rows (tid>>3)+32(i-2) ;
    // i=4,5 -> up rows (tid>>3)+32(i-4). dst = d0 + i*4096 (uniform).
    const int arow = tid >> 3;
    const int ach  = tid & 7;
    const uint32_t d0 = sb + (uint32_t)(arow * 128 + ((ach ^ (arow & 7)) << 4));
    const fp16* srcA0 = g_xsh + (size_t)STOK[arow]      * HID + ach * 8;
    const fp16* srcA1 = g_xsh + (size_t)STOK[arow + 32] * HID + ach * 8;
    const fp16* srcG  = wghb + (size_t)arow * HID + ach * 8;
    const fp16* srcU  = wuhb + (size_t)arow * HID + ach * 8;

    const uint32_t mloc = (lane & 7) | (((lane >> 3) & 1) << 3);
    const uint32_t csel = lane >> 4;
    const uint32_t wm = (wid & 1) * 32;
    const uint32_t wn = (wid >> 1) * 16;
    uint32_t aoff[2];
#pragma unroll
    for (int mt = 0; mt < 2; mt++) {
        uint32_t r = wm + mt * 16 + mloc;
        aoff[mt] = r * 128 + ((csel ^ (r & 7)) << 4);
    }
    const uint32_t brow = wn + mloc;
    const uint32_t boff = brow * 128 + ((csel ^ (brow & 7)) << 4);

    float cg[2][2][4] = {};
    float cu[2][2][4] = {};

    auto load_stage = [&](int stage, int k0) {
        const uint32_t st = d0 + stage * STAGE_BYTES;
        CPA(st,                 srcA0 + k0);
        CPA(st + 1 * 4096,      srcA1 + k0);
        CPA(st + 2 * 4096,      srcG  + k0);
        CPA(st + 3 * 4096,      srcG  + 32 * HID + k0);
        CPA(st + 4 * 4096,      srcU  + k0);
        CPA(st + 5 * 4096,      srcU  + 32 * HID + k0);
    };

    load_stage(0, 0); CPC();
    load_stage(1, 64); CPC();

    const int NC = HID / 64;
    int stage = 0;
    for (int kc = 0; kc < NC; kc++) {
        CPW(1);
        __syncthreads();
        if (kc + 2 < NC) {
            int ns = stage + 2; if (ns >= 3) ns -= 3;
            load_stage(ns, (kc + 2) * 64);
        }
        CPC();

        const uint32_t sA = sb + stage * STAGE_BYTES;
        const uint32_t sB = sA + 8192;
#pragma unroll
        for (int ks = 0; ks < 4; ks++) {
            const uint32_t x = ks << 5;
            uint32_t ah[2][4], gh[4], uh[4];
#pragma unroll
            for (int mt = 0; mt < 2; mt++) LDM4(ah[mt], sA + (aoff[mt] ^ x));
            LDM4(gh, sB + (boff ^ x));
            LDM4(uh, sB + 8192 + (boff ^ x));
#pragma unroll
            for (int mt = 0; mt < 2; mt++)
#pragma unroll
                for (int nt = 0; nt < 2; nt++) {
                    MMA(cg[mt][nt], ah[mt], gh[nt], gh[nt + 2]);
                    MMA(cu[mt][nt], ah[mt], uh[nt], uh[nt + 2]);
                }
        }
        if (++stage >= 3) stage = 0;
    }

    // epilogue: SiLU(g)*u -> fp16 act scratch
#pragma unroll
    for (int mt = 0; mt < 2; mt++) {
        int p0 = mtile * 64 + wm + mt * 16 + (lane >> 2);
        int p1 = p0 + 8;
#pragma unroll
        for (int nt = 0; nt < 2; nt++) {
            int col = ntile * 64 + wn + nt * 8 + (lane & 3) * 2;
            float a0, a1, a2, a3, gv, uv;
            gv = cg[mt][nt][0]; uv = cu[mt][nt][0]; a0 = gv / (1.f + expf(-gv)) * uv;
            gv = cg[mt][nt][1]; uv = cu[mt][nt][1]; a1 = gv / (1.f + expf(-gv)) * uv;
            gv = cg[mt][nt][2]; uv = cu[mt][nt][2]; a2 = gv / (1.f + expf(-gv)) * uv;
            gv = cg[mt][nt][3]; uv = cu[mt][nt][3]; a3 = gv / (1.f + expf(-gv)) * uv;
            if (p0 < cnt) {
                size_t idx = ((size_t)e * TOKS + p0) * INTD + col;
                __half2 hp;
                hp.x = __float2half_rn(a0); hp.y = __float2half_rn(a1);
                *(__half2*)(g_acth + idx) = hp;
            }
            if (p1 < cnt) {
                size_t idx = ((size_t)e * TOKS + p1) * INTD + col;
                __half2 hp;
                hp.x = __float2half_rn(a2); hp.y = __float2half_rn(a3);
                *(__half2*)(g_acth + idx) = hp;
            }
        }
    }
}

// ================= kernel: down GEMM + weighted scatter-add ===================
// CTA tile: M=64 slot rows x N=128 hid cols, K=INTD
__global__ void __launch_bounds__(256, 3)
k3_down(float* __restrict__ out) {
    extern __shared__ char smem[];
    const int e     = blockIdx.x >> 6;
    const int mtile = blockIdx.x & 63;
    const int ntile = blockIdx.y;
    const int cnt   = g_counts[e];
    if (mtile * 64 >= cnt) return;

    const int tid  = threadIdx.x;
    const int wid  = tid >> 5;
    const int lane = tid & 31;

    const uint32_t sb = smem_u32(smem);
    const fp16* ath = g_acth + (size_t)e * TOKS * INTD;
    const fp16* wdb = g_wdh + ((size_t)e * HID + (size_t)ntile * 128) * INTD;

    const int arow = tid >> 3;
    const int ach  = tid & 7;
    const uint32_t d0 = sb + (uint32_t)(arow * 128 + ((ach ^ (arow & 7)) << 4));
    int rp0 = mtile * 64 + arow;
    int rp1 = rp0 + 32;
    const fp16* srcA0 = ath + (size_t)(rp0 < cnt ? rp0 : cnt - 1) * INTD + ach * 8;
    const fp16* srcA1 = ath + (size_t)(rp1 < cnt ? rp1 : cnt - 1) * INTD + ach * 8;
    const fp16* srcB  = wdb + (size_t)arow * INTD + ach * 8;

    const uint32_t mloc = (lane & 7) | (((lane >> 3) & 1) << 3);
    const uint32_t csel = lane >> 4;
    const uint32_t wm = (wid & 1) * 32;
    const uint32_t wn = (wid >> 1) * 32;
    uint32_t aoff[2];
#pragma unroll
    for (int mt = 0; mt < 2; mt++) {
        uint32_t r = wm + mt * 16 + mloc;
        aoff[mt] = r * 128 + ((csel ^ (r & 7)) << 4);
    }
    uint32_t boff[2];
#pragma unroll
    for (int i = 0; i < 2; i++) {
        uint32_t r = wn + i * 16 + mloc;
        boff[i] = r * 128 + ((csel ^ (r & 7)) << 4);
    }

    float cd[2][4][4] = {};

    auto load_stage = [&](int stage, int k0) {
        const uint32_t st = d0 + stage * STAGE_BYTES;
        CPA(st,            srcA0 + k0);
        CPA(st + 1 * 4096, srcA1 + k0);
        CPA(st + 2 * 4096, srcB  + k0);
        CPA(st + 3 * 4096, srcB  + 32 * INTD + k0);
        CPA(st + 4 * 4096, srcB  + 64 * INTD + k0);
        CPA(st + 5 * 4096, srcB  + 96 * INTD + k0);
    };

    load_stage(0, 0); CPC();
    load_stage(1, 64); CPC();

    const int NC = INTD / 64;
    int stage = 0;
    for (int kc = 0; kc < NC; kc++) {
        CPW(1);
        __syncthreads();
        if (kc + 2 < NC) {
            int ns = stage + 2; if (ns >= 3) ns -= 3;
            load_stage(ns, (kc + 2) * 64);
        }
        CPC();

        const uint32_t sA = sb + stage * STAGE_BYTES;
        const uint32_t sB = sA + 8192;
#pragma unroll
        for (int ks = 0; ks < 4; ks++) {
            const uint32_t x = ks << 5;
            uint32_t ah[2][4], dh[8];
#pragma unroll
            for (int mt = 0; mt < 2; mt++) LDM4(ah[mt], sA + (aoff[mt] ^ x));
            LDM4(dh,     sB + (boff[0] ^ x));
            LDM4(dh + 4, sB + (boff[1] ^ x));
#pragma unroll
            for (int mt = 0; mt < 2; mt++)
#pragma unroll
                for (int nt = 0; nt < 4; nt++) {
                    int b0 = (nt >> 1) * 4 + (nt & 1);
                    MMA(cd[mt][nt], ah[mt], dh[b0], dh[b0 + 2]);
                }
        }
        if (++stage >= 3) stage = 0;
    }

    // epilogue: scale by routing weight, atomicAdd into out
#pragma unroll
    for (int mt = 0; mt < 2; mt++) {
        int p0 = mtile * 64 + wm + mt * 16 + (lane >> 2);
        int p1 = p0 + 8;
        bool v0 = p0 < cnt, v1 = p1 < cnt;
        float w0 = 0.f, w1 = 0.f;
        float *o0 = out, *o1 = out;
        if (v0) {
            w0 = g_wt[e * TOKS + p0];
            o0 = out + (size_t)g_tok[e * TOKS + p0] * HID + ntile * 128;
        }
        if (v1) {
            w1 = g_wt[e * TOKS + p1];
            o1 = out + (size_t)g_tok[e * TOKS + p1] * HID + ntile * 128;
        }
#pragma unroll
        for (int nt = 0; nt < 4; nt++) {
            int col = wn + nt * 8 + (lane & 3) * 2;
            if (v0) {
                atomicAdd(o0 + col,     w0 * cd[mt][nt][0]);
                atomicAdd(o0 + col + 1, w0 * cd[mt][nt][1]);
            }
            if (v1) {
                atomicAdd(o1 + col,     w1 * cd[mt][nt][2]);
                atomicAdd(o1 + col + 1, w1 * cd[mt][nt][3]);
            }
        }
    }
}

// ================= launch =====================================================
extern "C" void kernel_launch(void* const* d_in, const int* in_sizes, int n_in,
                              void* d_out, int out_size) {
    const float* x  = (const float*)d_in[0];
    const float* gw = (const float*)d_in[1];
    const float* wg = (const float*)d_in[2];
    const float* wu = (const float*)d_in[3];
    const float* wd = (const float*)d_in[4];
    float* out = (float*)d_out;

    const int SMEM = SMEM_MAIN + 512;
    cudaFuncSetAttribute(k2_gateup, cudaFuncAttributeMaxDynamicSharedMemorySize, SMEM);
    cudaFuncSetAttribute(k3_down,   cudaFuncAttributeMaxDynamicSharedMemorySize, SMEM);

    const int NCVT = (R_X + 3 * R_W) / 2;

    k_zero   <<<(TOKS * HID / 4 + 255) / 256, 256>>>((float4*)out, TOKS * HID / 4);
    k_router <<<TOKS / 8, 256>>>(x, gw);
    k_cvt_all<<<(NCVT + 255) / 256, 256>>>((const float4*)x, (const float4*)wg,
                                           (const float4*)wu, (const float4*)wd);
    k2_gateup<<<dim3(NE * 64, INTD / 64), 256, SMEM>>>();
    k3_down  <<<dim3(NE * 64, HID / 128), 256, SMEM>>>(out);
}